// round 2
// baseline (speedup 1.0000x reference)
#include <cuda_runtime.h>
#include <math.h>

#define E_N   4096
#define H_N   512
#define NH_N  4
#define HD_N  128
#define FFN_N 1024
#define H3_N  1536

// ---------------- scratch (static __device__, no allocs) ----------------
__device__ float g_msg [E_N * H_N];
__device__ float g_agg [E_N * H_N];
__device__ float g_gi  [E_N * H3_N];
__device__ float g_gh  [E_N * H3_N];
__device__ float g_h   [E_N * H_N];
__device__ float g_qkv [E_N * H3_N];
__device__ float g_attn[E_N * H_N];
__device__ float g_yprj[E_N * H_N];
__device__ float g_yn  [E_N * H_N];
__device__ float g_gact[E_N * H_N];
__device__ float g_f   [E_N * FFN_N];
__device__ int   g_idx64_flag;

// ---------------- zero ----------------
__global__ void zero_kernel(float* __restrict__ p, int n) {
    int i = blockIdx.x * blockDim.x + threadIdx.x;
    if (i < n) p[i] = 0.f;
}

// ---------------- edge-index dtype detection ----------------
// If edge_index is int64 (little-endian, values < 2^31), every odd 32-bit
// word is zero. If int32, odd words are random indices in [0, E).
__global__ void detect_idx_kernel(const int* __restrict__ ei32) {
    if (threadIdx.x == 0 && blockIdx.x == 0) {
        int allzero = 1;
#pragma unroll
        for (int i = 1; i < 16; i += 2)
            if (ei32[i] != 0) allzero = 0;
        g_idx64_flag = allzero;
    }
}

// ---------------- GEMM: C[M,N] = A[M,K] * B[N,K]^T + bias, optional ReLU ----
// 64x64 block tile, K-tile 16, 256 threads, 4x4 microtile.
template <bool RELU>
__global__ __launch_bounds__(256) void gemm_nt(
    const float* __restrict__ A, const float* __restrict__ B,
    const float* __restrict__ bias, float* __restrict__ C,
    int M, int N, int K)
{
    __shared__ float As[16][64];
    __shared__ float Bs[16][64];
    const int tid = threadIdx.x;
    const int tx = tid & 15, ty = tid >> 4;
    const int bm = blockIdx.y << 6, bn = blockIdx.x << 6;
    const int lr = tid >> 2;          // 0..63 row within tile
    const int lk = (tid & 3) << 2;    // 0,4,8,12 k within tile

    float acc[4][4];
#pragma unroll
    for (int i = 0; i < 4; i++)
#pragma unroll
        for (int j = 0; j < 4; j++) acc[i][j] = 0.f;

    const float* Ag = A + (size_t)(bm + lr) * K + lk;
    const float* Bg = B + (size_t)(bn + lr) * K + lk;

    for (int k0 = 0; k0 < K; k0 += 16) {
        float4 av = *(const float4*)(Ag + k0);
        float4 bv = *(const float4*)(Bg + k0);
        As[lk + 0][lr] = av.x; As[lk + 1][lr] = av.y;
        As[lk + 2][lr] = av.z; As[lk + 3][lr] = av.w;
        Bs[lk + 0][lr] = bv.x; Bs[lk + 1][lr] = bv.y;
        Bs[lk + 2][lr] = bv.z; Bs[lk + 3][lr] = bv.w;
        __syncthreads();
#pragma unroll
        for (int kk = 0; kk < 16; kk++) {
            float4 a = *(const float4*)&As[kk][ty << 2];
            float4 b = *(const float4*)&Bs[kk][tx << 2];
            float aa[4] = {a.x, a.y, a.z, a.w};
            float bb[4] = {b.x, b.y, b.z, b.w};
#pragma unroll
            for (int i = 0; i < 4; i++)
#pragma unroll
                for (int j = 0; j < 4; j++) acc[i][j] += aa[i] * bb[j];
        }
        __syncthreads();
    }
#pragma unroll
    for (int i = 0; i < 4; i++) {
        int row = bm + (ty << 2) + i;
#pragma unroll
        for (int j = 0; j < 4; j++) {
            int col = bn + (tx << 2) + j;
            float v = acc[i][j] + bias[col];
            if (RELU) v = fmaxf(v, 0.f);
            C[(size_t)row * N + col] = v;
        }
    }
}

// ---------------- scatter-add: agg[dst[e]] += msg[e] ----------------
__global__ void scatter_add_kernel(const void* __restrict__ ei) {
    int e = blockIdx.x;
    int dst;
    if (g_idx64_flag)
        dst = (int)((const long long*)ei)[E_N + e];
    else
        dst = ((const int*)ei)[E_N + e];
    if ((unsigned)dst >= (unsigned)E_N) return;  // safety: never OOB
    const float* src = g_msg + (size_t)e * H_N;
    float* d = g_agg + (size_t)dst * H_N;
    for (int i = threadIdx.x; i < H_N; i += blockDim.x)
        atomicAdd(&d[i], src[i]);
}

// ---------------- GRU elementwise ----------------
__global__ __launch_bounds__(256) void gru_kernel(const float* __restrict__ x) {
    int idx = blockIdx.x * blockDim.x + threadIdx.x;
    if (idx >= E_N * H_N) return;
    int e = idx / H_N, i = idx - e * H_N;
    const float* gi = g_gi + (size_t)e * H3_N;
    const float* gh = g_gh + (size_t)e * H3_N;
    float r = 1.f / (1.f + __expf(-(gi[i] + gh[i])));
    float z = 1.f / (1.f + __expf(-(gi[H_N + i] + gh[H_N + i])));
    float n = tanhf(gi[2 * H_N + i] + r * gh[2 * H_N + i]);
    g_h[idx] = (1.f - z) * n + z * x[idx];
}

// ---------------- flash-attention (fp32) ----------------
// grid: (E/128, NH), block 256. Q tile 128 rows, K/V tiles 64.
#define BR 128
#define BC 64
#define QPAD 132
#define KPAD 68
#define VPAD 132
#define SPAD 66
#define ATTN_SMEM_FLOATS (BR*QPAD + HD_N*KPAD + BC*VPAD + BR*SPAD + 3*BR)

__global__ __launch_bounds__(256) void attn_kernel() {
    extern __shared__ float sm[];
    float* Qs  = sm;                      // [BR][QPAD]  natural (r,d)
    float* Kt  = Qs + BR * QPAD;          // [HD][KPAD]  transposed (d,c)
    float* Vs  = Kt + HD_N * KPAD;        // [BC][VPAD]  natural (c,d)
    float* Ss  = Vs + BC * VPAD;          // [BR][SPAD]
    float* m_s = Ss + BR * SPAD;
    float* l_s = m_s + BR;
    float* a_s = l_s + BR;

    const int t = threadIdx.x;
    const int q0 = blockIdx.x * BR;
    const int head = blockIdx.y;
    const float scale = 0.08838834764831845f;  // 1/sqrt(128)

    // load Q tile
    for (int idx = t; idx < BR * (HD_N / 4); idx += 256) {
        int r = idx >> 5;
        int d4 = (idx & 31) << 2;
        float4 v = *(const float4*)&g_qkv[(size_t)(q0 + r) * H3_N + head * HD_N + d4];
        *(float4*)&Qs[r * QPAD + d4] = v;
    }
    if (t < BR) { m_s[t] = -1e30f; l_s[t] = 0.f; }

    const int ry = t >> 3;   // rows ry*4..  (PV & S share the row mapping)
    const int cx = t & 7;    // PV cols cx*16.. ; S cols cx*8..

    float oacc[4][16];
#pragma unroll
    for (int i = 0; i < 4; i++)
#pragma unroll
        for (int c = 0; c < 16; c++) oacc[i][c] = 0.f;

    __syncthreads();

    for (int j0 = 0; j0 < E_N; j0 += BC) {
        // load K (transposed) and V tiles
        for (int idx = t; idx < BC * (HD_N / 4); idx += 256) {
            int c = idx >> 5;
            int d4 = (idx & 31) << 2;
            float4 kv = *(const float4*)&g_qkv[(size_t)(j0 + c) * H3_N + H_N + head * HD_N + d4];
            Kt[(d4 + 0) * KPAD + c] = kv.x;
            Kt[(d4 + 1) * KPAD + c] = kv.y;
            Kt[(d4 + 2) * KPAD + c] = kv.z;
            Kt[(d4 + 3) * KPAD + c] = kv.w;
            float4 vv = *(const float4*)&g_qkv[(size_t)(j0 + c) * H3_N + 2 * H_N + head * HD_N + d4];
            *(float4*)&Vs[c * VPAD + d4] = vv;
        }
        __syncthreads();

        // ---- S = scale * Q K^T ----
        float sacc[4][8];
#pragma unroll
        for (int i = 0; i < 4; i++)
#pragma unroll
            for (int j = 0; j < 8; j++) sacc[i][j] = 0.f;

        for (int kk0 = 0; kk0 < HD_N; kk0 += 4) {
            float4 a4[4];
#pragma unroll
            for (int i = 0; i < 4; i++)
                a4[i] = *(const float4*)&Qs[(ry * 4 + i) * QPAD + kk0];
            const float* ap = reinterpret_cast<const float*>(a4);
#pragma unroll
            for (int kq = 0; kq < 4; kq++) {
                const float* krow = &Kt[(kk0 + kq) * KPAD + cx * 8];
                float4 b0 = *(const float4*)krow;
                float4 b1 = *(const float4*)(krow + 4);
                float bb[8] = {b0.x, b0.y, b0.z, b0.w, b1.x, b1.y, b1.z, b1.w};
#pragma unroll
                for (int i = 0; i < 4; i++) {
                    float av = ap[i * 4 + kq];
#pragma unroll
                    for (int j = 0; j < 8; j++) sacc[i][j] += av * bb[j];
                }
            }
        }
#pragma unroll
        for (int i = 0; i < 4; i++)
#pragma unroll
            for (int j = 0; j < 8; j++)
                Ss[(ry * 4 + i) * SPAD + cx * 8 + j] = sacc[i][j] * scale;
        __syncthreads();

        // ---- online softmax (2 threads per row) ----
        {
            int r = t >> 1, hb = (t & 1) * 32;
            float* srow = &Ss[r * SPAD + hb];
            float mloc = -1e30f;
#pragma unroll
            for (int i = 0; i < 32; i++) mloc = fmaxf(mloc, srow[i]);
            mloc = fmaxf(mloc, __shfl_xor_sync(0xffffffffu, mloc, 1));
            float mold = m_s[r];
            float mnew = fmaxf(mold, mloc);
            float ssum = 0.f;
#pragma unroll
            for (int i = 0; i < 32; i++) {
                float p = __expf(srow[i] - mnew);
                srow[i] = p;
                ssum += p;
            }
            ssum += __shfl_xor_sync(0xffffffffu, ssum, 1);
            if ((t & 1) == 0) {
                float alpha = __expf(mold - mnew);
                m_s[r] = mnew;
                l_s[r] = l_s[r] * alpha + ssum;
                a_s[r] = alpha;
            }
        }
        __syncthreads();

        // ---- O = O*alpha + P V ----
#pragma unroll
        for (int i = 0; i < 4; i++) {
            float al = a_s[ry * 4 + i];
#pragma unroll
            for (int c = 0; c < 16; c++) oacc[i][c] *= al;
        }
        for (int kk = 0; kk < BC; kk++) {
            const float* vrow = &Vs[kk * VPAD + cx * 16];
            float4 v0 = *(const float4*)(vrow + 0);
            float4 v1 = *(const float4*)(vrow + 4);
            float4 v2 = *(const float4*)(vrow + 8);
            float4 v3 = *(const float4*)(vrow + 12);
            float vv[16] = {v0.x, v0.y, v0.z, v0.w, v1.x, v1.y, v1.z, v1.w,
                            v2.x, v2.y, v2.z, v2.w, v3.x, v3.y, v3.z, v3.w};
#pragma unroll
            for (int i = 0; i < 4; i++) {
                float p = Ss[(ry * 4 + i) * SPAD + kk];
#pragma unroll
                for (int c = 0; c < 16; c++) oacc[i][c] += p * vv[c];
            }
        }
        __syncthreads();
    }

    // epilogue: divide by l, write concatenated-head output
#pragma unroll
    for (int i = 0; i < 4; i++) {
        int r = ry * 4 + i;
        float inv = 1.f / l_s[r];
        float* orow = &g_attn[(size_t)(q0 + r) * H_N + head * HD_N + cx * 16];
#pragma unroll
        for (int c4 = 0; c4 < 4; c4++) {
            float4 o;
            o.x = oacc[i][c4 * 4 + 0] * inv;
            o.y = oacc[i][c4 * 4 + 1] * inv;
            o.z = oacc[i][c4 * 4 + 2] * inv;
            o.w = oacc[i][c4 * 4 + 3] * inv;
            *(float4*)&orow[c4 * 4] = o;
        }
    }
}

// ---------------- residual + LayerNorm ----------------
__global__ __launch_bounds__(256) void ln_kernel(const float* __restrict__ ln_g,
                                                 const float* __restrict__ ln_b) {
    __shared__ float reda[8], redb[8];
    int e = blockIdx.x;
    const float* yp = g_yprj + (size_t)e * H_N;
    const float* hp = g_h + (size_t)e * H_N;
    int i0 = threadIdx.x, i1 = threadIdx.x + 256;
    float v0 = yp[i0] + hp[i0];
    float v1 = yp[i1] + hp[i1];
    float s = v0 + v1, s2 = v0 * v0 + v1 * v1;
#pragma unroll
    for (int o = 16; o > 0; o >>= 1) {
        s  += __shfl_down_sync(0xffffffffu, s, o);
        s2 += __shfl_down_sync(0xffffffffu, s2, o);
    }
    int w = threadIdx.x >> 5;
    if ((threadIdx.x & 31) == 0) { reda[w] = s; redb[w] = s2; }
    __syncthreads();
    if (threadIdx.x < 8) {
        s = reda[threadIdx.x]; s2 = redb[threadIdx.x];
#pragma unroll
        for (int o = 4; o > 0; o >>= 1) {
            s  += __shfl_down_sync(0xffu, s, o);
            s2 += __shfl_down_sync(0xffu, s2, o);
        }
        if (threadIdx.x == 0) { reda[0] = s; redb[0] = s2; }
    }
    __syncthreads();
    float mu = reda[0] * (1.f / H_N);
    float var = redb[0] * (1.f / H_N) - mu * mu;
    float rstd = rsqrtf(var + 1e-5f);
    g_yn[(size_t)e * H_N + i0] = (v0 - mu) * rstd * ln_g[i0] + ln_b[i0];
    g_yn[(size_t)e * H_N + i1] = (v1 - mu) * rstd * ln_g[i1] + ln_b[i1];
}

// ---------------- final dot: out[e] = f[e,:]·W_f2 + b_f2 ----------------
__global__ __launch_bounds__(256) void final_kernel(const float* __restrict__ W2,
                                                    const float* __restrict__ b2,
                                                    float* __restrict__ out) {
    __shared__ float red[8];
    int e = blockIdx.x;
    const float* fp = g_f + (size_t)e * FFN_N;
    float s = 0.f;
    for (int i = threadIdx.x; i < FFN_N; i += 256) s += fp[i] * W2[i];
#pragma unroll
    for (int o = 16; o > 0; o >>= 1) s += __shfl_down_sync(0xffffffffu, s, o);
    int w = threadIdx.x >> 5;
    if ((threadIdx.x & 31) == 0) red[w] = s;
    __syncthreads();
    if (threadIdx.x < 8) {
        s = red[threadIdx.x];
#pragma unroll
        for (int o = 4; o > 0; o >>= 1) s += __shfl_down_sync(0xffu, s, o);
        if (threadIdx.x == 0) out[e] = s + b2[0];
    }
}

// ---------------- launcher ----------------
extern "C" void kernel_launch(void* const* d_in, const int* in_sizes, int n_in,
                              void* d_out, int out_size) {
    const float* x       = (const float*)d_in[0];
    const void*  ei      = d_in[1];
    const float* W_msg   = (const float*)d_in[2];
    const float* b_msg   = (const float*)d_in[3];
    const float* W_ih    = (const float*)d_in[4];
    const float* b_ih    = (const float*)d_in[5];
    const float* W_hh    = (const float*)d_in[6];
    const float* b_hh    = (const float*)d_in[7];
    const float* W_inp   = (const float*)d_in[8];
    const float* b_inp   = (const float*)d_in[9];
    const float* W_outp  = (const float*)d_in[10];
    const float* b_outp  = (const float*)d_in[11];
    const float* ln_g    = (const float*)d_in[12];
    const float* ln_b    = (const float*)d_in[13];
    const float* W_lin   = (const float*)d_in[14];
    const float* b_lin   = (const float*)d_in[15];
    const float* W_f1    = (const float*)d_in[16];
    const float* b_f1    = (const float*)d_in[17];
    const float* W_f2    = (const float*)d_in[18];
    const float* b_f2    = (const float*)d_in[19];
    float* out = (float*)d_out;

    float *p_msg, *p_agg, *p_gi, *p_gh, *p_h, *p_qkv, *p_yn, *p_gact, *p_f;
    cudaGetSymbolAddress((void**)&p_msg,  g_msg);
    cudaGetSymbolAddress((void**)&p_agg,  g_agg);
    cudaGetSymbolAddress((void**)&p_gi,   g_gi);
    cudaGetSymbolAddress((void**)&p_gh,   g_gh);
    cudaGetSymbolAddress((void**)&p_h,    g_h);
    cudaGetSymbolAddress((void**)&p_qkv,  g_qkv);
    cudaGetSymbolAddress((void**)&p_yn,   g_yn);
    cudaGetSymbolAddress((void**)&p_gact, g_gact);
    cudaGetSymbolAddress((void**)&p_f,    g_f);
    float *p_attn, *p_yprj;
    cudaGetSymbolAddress((void**)&p_attn, g_attn);
    cudaGetSymbolAddress((void**)&p_yprj, g_yprj);

    // 0) detect edge_index dtype (int32 vs int64 transport)
    detect_idx_kernel<<<1, 32>>>((const int*)ei);
    // 1) zero agg
    zero_kernel<<<(E_N * H_N + 255) / 256, 256>>>(p_agg, E_N * H_N);
    // 2) msg = relu(x @ W_msg^T + b)
    gemm_nt<true><<<dim3(H_N / 64, E_N / 64), 256>>>(x, W_msg, b_msg, p_msg, E_N, H_N, H_N);
    // 3) scatter-add into agg
    scatter_add_kernel<<<E_N, 128>>>(ei);
    // 4) gi = agg @ W_ih^T + b_ih ; gh = x @ W_hh^T + b_hh
    gemm_nt<false><<<dim3(H3_N / 64, E_N / 64), 256>>>(p_agg, W_ih, b_ih, p_gi, E_N, H3_N, H_N);
    gemm_nt<false><<<dim3(H3_N / 64, E_N / 64), 256>>>(x, W_hh, b_hh, p_gh, E_N, H3_N, H_N);
    // 5) GRU -> h
    gru_kernel<<<(E_N * H_N + 255) / 256, 256>>>(x);
    // 6) qkv = h @ W_in_proj^T + b
    gemm_nt<false><<<dim3(H3_N / 64, E_N / 64), 256>>>(p_h, W_inp, b_inp, p_qkv, E_N, H3_N, H_N);
    // 7) attention
    size_t attn_smem = ATTN_SMEM_FLOATS * sizeof(float);
    cudaFuncSetAttribute(attn_kernel, cudaFuncAttributeMaxDynamicSharedMemorySize, (int)attn_smem);
    attn_kernel<<<dim3(E_N / BR, NH_N), 256, attn_smem>>>();
    // 8) out-proj
    gemm_nt<false><<<dim3(H_N / 64, E_N / 64), 256>>>(p_attn, W_outp, b_outp, p_yprj, E_N, H_N, H_N);
    // 9) residual + LN
    ln_kernel<<<E_N, 256>>>(ln_g, ln_b);
    // 10) g = relu(yn @ W_lin^T + b)
    gemm_nt<true><<<dim3(H_N / 64, E_N / 64), 256>>>(p_yn, W_lin, b_lin, p_gact, E_N, H_N, H_N);
    // 11) f = relu(g @ W_f1^T + b_f1)
    gemm_nt<true><<<dim3(FFN_N / 64, E_N / 64), 256>>>(p_gact, W_f1, b_f1, p_f, E_N, FFN_N, H_N);
    // 12) out = f @ W_f2^T + b_f2
    final_kernel<<<E_N, 256>>>(W_f2, b_f2, out);
}

// round 4
// speedup vs baseline: 1.1752x; 1.1752x over previous
#include <cuda_runtime.h>
#include <math.h>
#include <stdint.h>

#define E_N   4096
#define H_N   512
#define NH_N  4
#define HD_N  128
#define FFN_N 1024
#define H3_N  1536

// ---------------- scratch (static __device__, no allocs) ----------------
__device__ float g_msg [E_N * H_N];
__device__ float g_agg [E_N * H_N];
__device__ float g_gi  [E_N * H3_N];
__device__ float g_gh  [E_N * H3_N];
__device__ float g_h   [E_N * H_N];
__device__ float g_qkv [E_N * H3_N];
__device__ float g_attn[E_N * H_N];
__device__ float g_yprj[E_N * H_N];
__device__ float g_yn  [E_N * H_N];
__device__ float g_gact[E_N * H_N];
__device__ float g_f   [E_N * FFN_N];
__device__ int   g_idx64_flag;

// ================= mma.sync tf32 helpers (portable PTX, sm_80+) =========
__device__ __forceinline__ uint32_t f2tf32(float f) {
    uint32_t r;
    asm("cvt.rna.tf32.f32 %0, %1;" : "=r"(r) : "f"(f));
    return r;
}

__device__ __forceinline__ void mma_tf32(float* d, const uint32_t* a, const uint32_t* b) {
    asm volatile(
        "mma.sync.aligned.m16n8k8.row.col.f32.tf32.tf32.f32 "
        "{%0,%1,%2,%3}, {%4,%5,%6,%7}, {%8,%9}, {%0,%1,%2,%3};"
        : "+f"(d[0]), "+f"(d[1]), "+f"(d[2]), "+f"(d[3])
        : "r"(a[0]), "r"(a[1]), "r"(a[2]), "r"(a[3]),
          "r"(b[0]), "r"(b[1]));
}

// ================= tensor-core tf32x3 GEMM ==============================
// C[M,N] = A[M,K] @ B[N,K]^T + bias, optional ReLU.
// CTA tile 128x128, 8 warps in 2(M) x 4(N); warp tile 64x32 = 4x4 m16n8 tiles.
// K chunk = 32 fp32 in smem (hi/lo tf32 split); register prefetch of next chunk.

#define KC      32
#define SSTRIDE 36                       // 32 + 4 pad (floats)
#define BUF_FLOATS (128 * SSTRIDE)       // 4608 floats per buffer
#define OFF_AHI 0
#define OFF_ALO (BUF_FLOATS)
#define OFF_BHI (2 * BUF_FLOATS)
#define OFF_BLO (3 * BUF_FLOATS)
#define GEMM_SMEM_BYTES (4 * BUF_FLOATS * 4)   // 73728

template <bool RELU>
__global__ __launch_bounds__(256) void gemm_mma(
    const float* __restrict__ A, const float* __restrict__ B,
    const float* __restrict__ bias, float* __restrict__ C,
    int N, int K)
{
    extern __shared__ float sm[];
    uint32_t* AHI = (uint32_t*)(sm + OFF_AHI);
    uint32_t* ALO = (uint32_t*)(sm + OFF_ALO);
    uint32_t* BHI = (uint32_t*)(sm + OFF_BHI);
    uint32_t* BLO = (uint32_t*)(sm + OFF_BLO);

    const int tid  = threadIdx.x;
    const int lane = tid & 31;
    const int wid  = tid >> 5;
    const int wm64 = (wid >> 2) << 6;    // warp M offset: 0 or 64
    const int wn32 = (wid & 3) << 5;     // warp N offset: 0,32,64,96
    const int bm = blockIdx.y << 7;
    const int bn = blockIdx.x << 7;

    // per-thread load coordinates: 4 float4 per operand per chunk
    // i = tid + it*256 in [0,1024): row = i>>3, colf = (i&7)*4
    float4 rA[4], rB[4];

    const int NKC = K >> 5;

    // prefetch chunk 0
#pragma unroll
    for (int it = 0; it < 4; it++) {
        int i = tid + (it << 8);
        int r = i >> 3, cf = (i & 7) << 2;
        rA[it] = *(const float4*)(A + (size_t)(bm + r) * K + cf);
        rB[it] = *(const float4*)(B + (size_t)(bn + r) * K + cf);
    }

    float acc[4][4][4];
#pragma unroll
    for (int mt = 0; mt < 4; mt++)
#pragma unroll
        for (int nt = 0; nt < 4; nt++)
#pragma unroll
            for (int c = 0; c < 4; c++) acc[mt][nt][c] = 0.f;

    for (int kc = 0; kc < NKC; kc++) {
        // ---- store prefetched chunk to smem with tf32 hi/lo split ----
#pragma unroll
        for (int it = 0; it < 4; it++) {
            int i = tid + (it << 8);
            int r = i >> 3, cf = (i & 7) << 2;
            int off = r * SSTRIDE + cf;
            uint4 hi, lo;
            hi.x = f2tf32(rA[it].x); lo.x = f2tf32(rA[it].x - __uint_as_float(hi.x));
            hi.y = f2tf32(rA[it].y); lo.y = f2tf32(rA[it].y - __uint_as_float(hi.y));
            hi.z = f2tf32(rA[it].z); lo.z = f2tf32(rA[it].z - __uint_as_float(hi.z));
            hi.w = f2tf32(rA[it].w); lo.w = f2tf32(rA[it].w - __uint_as_float(hi.w));
            *(uint4*)(AHI + off) = hi;
            *(uint4*)(ALO + off) = lo;
            hi.x = f2tf32(rB[it].x); lo.x = f2tf32(rB[it].x - __uint_as_float(hi.x));
            hi.y = f2tf32(rB[it].y); lo.y = f2tf32(rB[it].y - __uint_as_float(hi.y));
            hi.z = f2tf32(rB[it].z); lo.z = f2tf32(rB[it].z - __uint_as_float(hi.z));
            hi.w = f2tf32(rB[it].w); lo.w = f2tf32(rB[it].w - __uint_as_float(hi.w));
            *(uint4*)(BHI + off) = hi;
            *(uint4*)(BLO + off) = lo;
        }
        __syncthreads();

        // ---- prefetch next chunk (global latency overlaps mma) ----
        if (kc + 1 < NKC) {
            int k0 = (kc + 1) << 5;
#pragma unroll
            for (int it = 0; it < 4; it++) {
                int i = tid + (it << 8);
                int r = i >> 3, cf = (i & 7) << 2;
                rA[it] = *(const float4*)(A + (size_t)(bm + r) * K + k0 + cf);
                rB[it] = *(const float4*)(B + (size_t)(bn + r) * K + k0 + cf);
            }
        }

        // ---- compute: 4 k8-steps, tf32x3 ----
#pragma unroll
        for (int kk = 0; kk < 4; kk++) {
            const int kcol = (kk << 3) + (lane & 3);
            uint32_t ahi[4][4], alo[4][4], bhi[4][2], blo[4][2];
#pragma unroll
            for (int mt = 0; mt < 4; mt++) {
                int base = (wm64 + (mt << 4) + (lane >> 2)) * SSTRIDE + kcol;
                ahi[mt][0] = AHI[base];
                ahi[mt][1] = AHI[base + 8 * SSTRIDE];
                ahi[mt][2] = AHI[base + 4];
                ahi[mt][3] = AHI[base + 8 * SSTRIDE + 4];
                alo[mt][0] = ALO[base];
                alo[mt][1] = ALO[base + 8 * SSTRIDE];
                alo[mt][2] = ALO[base + 4];
                alo[mt][3] = ALO[base + 8 * SSTRIDE + 4];
            }
#pragma unroll
            for (int nt = 0; nt < 4; nt++) {
                int base = (wn32 + (nt << 3) + (lane >> 2)) * SSTRIDE + kcol;
                bhi[nt][0] = BHI[base];
                bhi[nt][1] = BHI[base + 4];
                blo[nt][0] = BLO[base];
                blo[nt][1] = BLO[base + 4];
            }
#pragma unroll
            for (int mt = 0; mt < 4; mt++)
#pragma unroll
                for (int nt = 0; nt < 4; nt++)
                    mma_tf32(acc[mt][nt], ahi[mt], bhi[nt]);
#pragma unroll
            for (int mt = 0; mt < 4; mt++)
#pragma unroll
                for (int nt = 0; nt < 4; nt++)
                    mma_tf32(acc[mt][nt], ahi[mt], blo[nt]);
#pragma unroll
            for (int mt = 0; mt < 4; mt++)
#pragma unroll
                for (int nt = 0; nt < 4; nt++)
                    mma_tf32(acc[mt][nt], alo[mt], bhi[nt]);
        }
        __syncthreads();
    }

    // ---- epilogue: bias (+ReLU) and store ----
#pragma unroll
    for (int mt = 0; mt < 4; mt++) {
        int row0 = bm + wm64 + (mt << 4) + (lane >> 2);
#pragma unroll
        for (int nt = 0; nt < 4; nt++) {
            int col0 = bn + wn32 + (nt << 3) + ((lane & 3) << 1);
            float b0 = bias[col0], b1 = bias[col0 + 1];
            float2 v0 = make_float2(acc[mt][nt][0] + b0, acc[mt][nt][1] + b1);
            float2 v1 = make_float2(acc[mt][nt][2] + b0, acc[mt][nt][3] + b1);
            if (RELU) {
                v0.x = fmaxf(v0.x, 0.f); v0.y = fmaxf(v0.y, 0.f);
                v1.x = fmaxf(v1.x, 0.f); v1.y = fmaxf(v1.y, 0.f);
            }
            *(float2*)(C + (size_t)row0 * N + col0) = v0;
            *(float2*)(C + (size_t)(row0 + 8) * N + col0) = v1;
        }
    }
}

// ---------------- zero ----------------
__global__ void zero_kernel(float* __restrict__ p, int n) {
    int i = blockIdx.x * blockDim.x + threadIdx.x;
    if (i < n) p[i] = 0.f;
}

// ---------------- edge-index dtype detection ----------------
__global__ void detect_idx_kernel(const int* __restrict__ ei32) {
    if (threadIdx.x == 0 && blockIdx.x == 0) {
        int allzero = 1;
#pragma unroll
        for (int i = 1; i < 16; i += 2)
            if (ei32[i] != 0) allzero = 0;
        g_idx64_flag = allzero;
    }
}

// ---------------- scatter-add ----------------
__global__ void scatter_add_kernel(const void* __restrict__ ei) {
    int e = blockIdx.x;
    int dst;
    if (g_idx64_flag)
        dst = (int)((const long long*)ei)[E_N + e];
    else
        dst = ((const int*)ei)[E_N + e];
    if ((unsigned)dst >= (unsigned)E_N) return;
    const float* src = g_msg + (size_t)e * H_N;
    float* d = g_agg + (size_t)dst * H_N;
    for (int i = threadIdx.x; i < H_N; i += blockDim.x)
        atomicAdd(&d[i], src[i]);
}

// ---------------- GRU elementwise ----------------
__global__ __launch_bounds__(256) void gru_kernel(const float* __restrict__ x) {
    int idx = blockIdx.x * blockDim.x + threadIdx.x;
    if (idx >= E_N * H_N) return;
    int e = idx / H_N, i = idx - e * H_N;
    const float* gi = g_gi + (size_t)e * H3_N;
    const float* gh = g_gh + (size_t)e * H3_N;
    float r = 1.f / (1.f + __expf(-(gi[i] + gh[i])));
    float z = 1.f / (1.f + __expf(-(gi[H_N + i] + gh[H_N + i])));
    float n = tanhf(gi[2 * H_N + i] + r * gh[2 * H_N + i]);
    g_h[idx] = (1.f - z) * n + z * x[idx];
}

// ---------------- flash-attention (fp32) ----------------
#define BR 128
#define BC 64
#define QPAD 132
#define KPAD 68
#define VPAD 132
#define SPAD 66
#define ATTN_SMEM_FLOATS (BR*QPAD + HD_N*KPAD + BC*VPAD + BR*SPAD + 3*BR)

__global__ __launch_bounds__(256) void attn_kernel() {
    extern __shared__ float smf[];
    float* Qs  = smf;
    float* Kt  = Qs + BR * QPAD;
    float* Vs  = Kt + HD_N * KPAD;
    float* Ss  = Vs + BC * VPAD;
    float* m_s = Ss + BR * SPAD;
    float* l_s = m_s + BR;
    float* a_s = l_s + BR;

    const int t = threadIdx.x;
    const int q0 = blockIdx.x * BR;
    const int head = blockIdx.y;
    const float scale = 0.08838834764831845f;

    for (int idx = t; idx < BR * (HD_N / 4); idx += 256) {
        int r = idx >> 5;
        int d4 = (idx & 31) << 2;
        float4 v = *(const float4*)&g_qkv[(size_t)(q0 + r) * H3_N + head * HD_N + d4];
        *(float4*)&Qs[r * QPAD + d4] = v;
    }
    if (t < BR) { m_s[t] = -1e30f; l_s[t] = 0.f; }

    const int ry = t >> 3;
    const int cx = t & 7;

    float oacc[4][16];
#pragma unroll
    for (int i = 0; i < 4; i++)
#pragma unroll
        for (int c = 0; c < 16; c++) oacc[i][c] = 0.f;

    __syncthreads();

    for (int j0 = 0; j0 < E_N; j0 += BC) {
        for (int idx = t; idx < BC * (HD_N / 4); idx += 256) {
            int c = idx >> 5;
            int d4 = (idx & 31) << 2;
            float4 kv = *(const float4*)&g_qkv[(size_t)(j0 + c) * H3_N + H_N + head * HD_N + d4];
            Kt[(d4 + 0) * KPAD + c] = kv.x;
            Kt[(d4 + 1) * KPAD + c] = kv.y;
            Kt[(d4 + 2) * KPAD + c] = kv.z;
            Kt[(d4 + 3) * KPAD + c] = kv.w;
            float4 vv = *(const float4*)&g_qkv[(size_t)(j0 + c) * H3_N + 2 * H_N + head * HD_N + d4];
            *(float4*)&Vs[c * VPAD + d4] = vv;
        }
        __syncthreads();

        float sacc[4][8];
#pragma unroll
        for (int i = 0; i < 4; i++)
#pragma unroll
            for (int j = 0; j < 8; j++) sacc[i][j] = 0.f;

        for (int kk0 = 0; kk0 < HD_N; kk0 += 4) {
            float4 a4[4];
#pragma unroll
            for (int i = 0; i < 4; i++)
                a4[i] = *(const float4*)&Qs[(ry * 4 + i) * QPAD + kk0];
            const float* ap = reinterpret_cast<const float*>(a4);
#pragma unroll
            for (int kq = 0; kq < 4; kq++) {
                const float* krow = &Kt[(kk0 + kq) * KPAD + cx * 8];
                float4 b0 = *(const float4*)krow;
                float4 b1 = *(const float4*)(krow + 4);
                float bb[8] = {b0.x, b0.y, b0.z, b0.w, b1.x, b1.y, b1.z, b1.w};
#pragma unroll
                for (int i = 0; i < 4; i++) {
                    float av = ap[i * 4 + kq];
#pragma unroll
                    for (int j = 0; j < 8; j++) sacc[i][j] += av * bb[j];
                }
            }
        }
#pragma unroll
        for (int i = 0; i < 4; i++)
#pragma unroll
            for (int j = 0; j < 8; j++)
                Ss[(ry * 4 + i) * SPAD + cx * 8 + j] = sacc[i][j] * scale;
        __syncthreads();

        {
            int r = t >> 1, hb = (t & 1) * 32;
            float* srow = &Ss[r * SPAD + hb];
            float mloc = -1e30f;
#pragma unroll
            for (int i = 0; i < 32; i++) mloc = fmaxf(mloc, srow[i]);
            mloc = fmaxf(mloc, __shfl_xor_sync(0xffffffffu, mloc, 1));
            float mold = m_s[r];
            float mnew = fmaxf(mold, mloc);
            float ssum = 0.f;
#pragma unroll
            for (int i = 0; i < 32; i++) {
                float p = __expf(srow[i] - mnew);
                srow[i] = p;
                ssum += p;
            }
            ssum += __shfl_xor_sync(0xffffffffu, ssum, 1);
            if ((t & 1) == 0) {
                float alpha = __expf(mold - mnew);
                m_s[r] = mnew;
                l_s[r] = l_s[r] * alpha + ssum;
                a_s[r] = alpha;
            }
        }
        __syncthreads();

#pragma unroll
        for (int i = 0; i < 4; i++) {
            float al = a_s[ry * 4 + i];
#pragma unroll
            for (int c = 0; c < 16; c++) oacc[i][c] *= al;
        }
        for (int kk = 0; kk < BC; kk++) {
            const float* vrow = &Vs[kk * VPAD + cx * 16];
            float4 v0 = *(const float4*)(vrow + 0);
            float4 v1 = *(const float4*)(vrow + 4);
            float4 v2 = *(const float4*)(vrow + 8);
            float4 v3 = *(const float4*)(vrow + 12);
            float vv[16] = {v0.x, v0.y, v0.z, v0.w, v1.x, v1.y, v1.z, v1.w,
                            v2.x, v2.y, v2.z, v2.w, v3.x, v3.y, v3.z, v3.w};
#pragma unroll
            for (int i = 0; i < 4; i++) {
                float p = Ss[(ry * 4 + i) * SPAD + kk];
#pragma unroll
                for (int c = 0; c < 16; c++) oacc[i][c] += p * vv[c];
            }
        }
        __syncthreads();
    }

#pragma unroll
    for (int i = 0; i < 4; i++) {
        int r = ry * 4 + i;
        float inv = 1.f / l_s[r];
        float* orow = &g_attn[(size_t)(q0 + r) * H_N + head * HD_N + cx * 16];
#pragma unroll
        for (int c4 = 0; c4 < 4; c4++) {
            float4 o;
            o.x = oacc[i][c4 * 4 + 0] * inv;
            o.y = oacc[i][c4 * 4 + 1] * inv;
            o.z = oacc[i][c4 * 4 + 2] * inv;
            o.w = oacc[i][c4 * 4 + 3] * inv;
            *(float4*)&orow[c4 * 4] = o;
        }
    }
}

// ---------------- residual + LayerNorm ----------------
__global__ __launch_bounds__(256) void ln_kernel(const float* __restrict__ ln_g,
                                                 const float* __restrict__ ln_b) {
    __shared__ float reda[8], redb[8];
    int e = blockIdx.x;
    const float* yp = g_yprj + (size_t)e * H_N;
    const float* hp = g_h + (size_t)e * H_N;
    int i0 = threadIdx.x, i1 = threadIdx.x + 256;
    float v0 = yp[i0] + hp[i0];
    float v1 = yp[i1] + hp[i1];
    float s = v0 + v1, s2 = v0 * v0 + v1 * v1;
#pragma unroll
    for (int o = 16; o > 0; o >>= 1) {
        s  += __shfl_down_sync(0xffffffffu, s, o);
        s2 += __shfl_down_sync(0xffffffffu, s2, o);
    }
    int w = threadIdx.x >> 5;
    if ((threadIdx.x & 31) == 0) { reda[w] = s; redb[w] = s2; }
    __syncthreads();
    if (threadIdx.x < 8) {
        s = reda[threadIdx.x]; s2 = redb[threadIdx.x];
#pragma unroll
        for (int o = 4; o > 0; o >>= 1) {
            s  += __shfl_down_sync(0xffu, s, o);
            s2 += __shfl_down_sync(0xffu, s2, o);
        }
        if (threadIdx.x == 0) { reda[0] = s; redb[0] = s2; }
    }
    __syncthreads();
    float mu = reda[0] * (1.f / H_N);
    float var = redb[0] * (1.f / H_N) - mu * mu;
    float rstd = rsqrtf(var + 1e-5f);
    g_yn[(size_t)e * H_N + i0] = (v0 - mu) * rstd * ln_g[i0] + ln_b[i0];
    g_yn[(size_t)e * H_N + i1] = (v1 - mu) * rstd * ln_g[i1] + ln_b[i1];
}

// ---------------- final dot ----------------
__global__ __launch_bounds__(256) void final_kernel(const float* __restrict__ W2,
                                                    const float* __restrict__ b2,
                                                    float* __restrict__ out) {
    __shared__ float red[8];
    int e = blockIdx.x;
    const float* fp = g_f + (size_t)e * FFN_N;
    float s = 0.f;
    for (int i = threadIdx.x; i < FFN_N; i += 256) s += fp[i] * W2[i];
#pragma unroll
    for (int o = 16; o > 0; o >>= 1) s += __shfl_down_sync(0xffffffffu, s, o);
    int w = threadIdx.x >> 5;
    if ((threadIdx.x & 31) == 0) red[w] = s;
    __syncthreads();
    if (threadIdx.x < 8) {
        s = red[threadIdx.x];
#pragma unroll
        for (int o = 4; o > 0; o >>= 1) s += __shfl_down_sync(0xffu, s, o);
        if (threadIdx.x == 0) out[e] = s + b2[0];
    }
}

// ---------------- launcher ----------------
extern "C" void kernel_launch(void* const* d_in, const int* in_sizes, int n_in,
                              void* d_out, int out_size) {
    const float* x       = (const float*)d_in[0];
    const void*  ei      = d_in[1];
    const float* W_msg   = (const float*)d_in[2];
    const float* b_msg   = (const float*)d_in[3];
    const float* W_ih    = (const float*)d_in[4];
    const float* b_ih    = (const float*)d_in[5];
    const float* W_hh    = (const float*)d_in[6];
    const float* b_hh    = (const float*)d_in[7];
    const float* W_inp   = (const float*)d_in[8];
    const float* b_inp   = (const float*)d_in[9];
    const float* W_outp  = (const float*)d_in[10];
    const float* b_outp  = (const float*)d_in[11];
    const float* ln_g    = (const float*)d_in[12];
    const float* ln_b    = (const float*)d_in[13];
    const float* W_lin   = (const float*)d_in[14];
    const float* b_lin   = (const float*)d_in[15];
    const float* W_f1    = (const float*)d_in[16];
    const float* b_f1    = (const float*)d_in[17];
    const float* W_f2    = (const float*)d_in[18];
    const float* b_f2    = (const float*)d_in[19];
    float* out = (float*)d_out;

    float *p_msg, *p_agg, *p_gi, *p_gh, *p_h, *p_qkv, *p_yn, *p_gact, *p_f;
    float *p_attn, *p_yprj;
    cudaGetSymbolAddress((void**)&p_msg,  g_msg);
    cudaGetSymbolAddress((void**)&p_agg,  g_agg);
    cudaGetSymbolAddress((void**)&p_gi,   g_gi);
    cudaGetSymbolAddress((void**)&p_gh,   g_gh);
    cudaGetSymbolAddress((void**)&p_h,    g_h);
    cudaGetSymbolAddress((void**)&p_qkv,  g_qkv);
    cudaGetSymbolAddress((void**)&p_yn,   g_yn);
    cudaGetSymbolAddress((void**)&p_gact, g_gact);
    cudaGetSymbolAddress((void**)&p_f,    g_f);
    cudaGetSymbolAddress((void**)&p_attn, g_attn);
    cudaGetSymbolAddress((void**)&p_yprj, g_yprj);

    cudaFuncSetAttribute(gemm_mma<false>, cudaFuncAttributeMaxDynamicSharedMemorySize, GEMM_SMEM_BYTES);
    cudaFuncSetAttribute(gemm_mma<true>,  cudaFuncAttributeMaxDynamicSharedMemorySize, GEMM_SMEM_BYTES);

    // 0) detect edge_index dtype
    detect_idx_kernel<<<1, 32>>>((const int*)ei);
    // 1) zero agg
    zero_kernel<<<(E_N * H_N + 255) / 256, 256>>>(p_agg, E_N * H_N);
    // 2) msg = relu(x @ W_msg^T + b)
    gemm_mma<true><<<dim3(H_N / 128, E_N / 128), 256, GEMM_SMEM_BYTES>>>(x, W_msg, b_msg, p_msg, H_N, H_N);
    // 3) scatter-add
    scatter_add_kernel<<<E_N, 128>>>(ei);
    // 4) gi, gh
    gemm_mma<false><<<dim3(H3_N / 128, E_N / 128), 256, GEMM_SMEM_BYTES>>>(p_agg, W_ih, b_ih, p_gi, H3_N, H_N);
    gemm_mma<false><<<dim3(H3_N / 128, E_N / 128), 256, GEMM_SMEM_BYTES>>>(x, W_hh, b_hh, p_gh, H3_N, H_N);
    // 5) GRU
    gru_kernel<<<(E_N * H_N + 255) / 256, 256>>>(x);
    // 6) qkv
    gemm_mma<false><<<dim3(H3_N / 128, E_N / 128), 256, GEMM_SMEM_BYTES>>>(p_h, W_inp, b_inp, p_qkv, H3_N, H_N);
    // 7) attention
    size_t attn_smem = ATTN_SMEM_FLOATS * sizeof(float);
    cudaFuncSetAttribute(attn_kernel, cudaFuncAttributeMaxDynamicSharedMemorySize, (int)attn_smem);
    attn_kernel<<<dim3(E_N / BR, NH_N), 256, attn_smem>>>();
    // 8) out-proj
    gemm_mma<false><<<dim3(H_N / 128, E_N / 128), 256, GEMM_SMEM_BYTES>>>(p_attn, W_outp, b_outp, p_yprj, H_N, H_N);
    // 9) residual + LN
    ln_kernel<<<E_N, 256>>>(ln_g, ln_b);
    // 10) g = relu(yn @ W_lin^T + b)
    gemm_mma<true><<<dim3(H_N / 128, E_N / 128), 256, GEMM_SMEM_BYTES>>>(p_yn, W_lin, b_lin, p_gact, H_N, H_N);
    // 11) f = relu(g @ W_f1^T + b_f1)
    gemm_mma<true><<<dim3(FFN_N / 128, E_N / 128), 256, GEMM_SMEM_BYTES>>>(p_gact, W_f1, b_f1, p_f, FFN_N, H_N);
    // 12) out
    final_kernel<<<E_N, 256>>>(W_f2, b_f2, out);
}

// round 5
// speedup vs baseline: 2.1711x; 1.8475x over previous
#include <cuda_runtime.h>
#include <math.h>
#include <stdint.h>

#define E_N   4096
#define H_N   512
#define NH_N  4
#define HD_N  128
#define FFN_N 1024
#define H3_N  1536

// ---------------- scratch (static __device__, no allocs) ----------------
__device__ float g_msg [E_N * H_N];
__device__ float g_agg [E_N * H_N];
__device__ float g_gi  [E_N * H3_N];
__device__ float g_gh  [E_N * H3_N];
__device__ float g_h   [E_N * H_N];
__device__ float g_qkv [E_N * H3_N];
__device__ float g_attn[E_N * H_N];
__device__ float g_yprj[E_N * H_N];
__device__ float g_yn  [E_N * H_N];
__device__ float g_gact[E_N * H_N];
__device__ float g_f   [E_N * FFN_N];
__device__ int   g_idx64_flag;
// tf32 hi/lo split planes, per-head layout [NH][E][HD]
__device__ uint32_t g_qhi[NH_N * E_N * HD_N];
__device__ uint32_t g_qlo[NH_N * E_N * HD_N];
__device__ uint32_t g_khi[NH_N * E_N * HD_N];
__device__ uint32_t g_klo[NH_N * E_N * HD_N];
__device__ uint32_t g_vhi[NH_N * E_N * HD_N];
__device__ uint32_t g_vlo[NH_N * E_N * HD_N];

// ================= mma.sync tf32 helpers (portable PTX, sm_80+) =========
__device__ __forceinline__ uint32_t f2tf32(float f) {
    uint32_t r;
    asm("cvt.rna.tf32.f32 %0, %1;" : "=r"(r) : "f"(f));
    return r;
}

__device__ __forceinline__ void mma_tf32(float* d, const uint32_t* a, const uint32_t* b) {
    asm volatile(
        "mma.sync.aligned.m16n8k8.row.col.f32.tf32.tf32.f32 "
        "{%0,%1,%2,%3}, {%4,%5,%6,%7}, {%8,%9}, {%0,%1,%2,%3};"
        : "+f"(d[0]), "+f"(d[1]), "+f"(d[2]), "+f"(d[3])
        : "r"(a[0]), "r"(a[1]), "r"(a[2]), "r"(a[3]),
          "r"(b[0]), "r"(b[1]));
}

// ================= tensor-core tf32x3 GEMM ==============================
#define SSTRIDE 36
#define BUF_FLOATS (128 * SSTRIDE)
#define OFF_AHI 0
#define OFF_ALO (BUF_FLOATS)
#define OFF_BHI (2 * BUF_FLOATS)
#define OFF_BLO (3 * BUF_FLOATS)
#define GEMM_SMEM_BYTES (4 * BUF_FLOATS * 4)

template <bool RELU>
__global__ __launch_bounds__(256) void gemm_mma(
    const float* __restrict__ A, const float* __restrict__ B,
    const float* __restrict__ bias, float* __restrict__ C,
    int N, int K)
{
    extern __shared__ float sm[];
    uint32_t* AHI = (uint32_t*)(sm + OFF_AHI);
    uint32_t* ALO = (uint32_t*)(sm + OFF_ALO);
    uint32_t* BHI = (uint32_t*)(sm + OFF_BHI);
    uint32_t* BLO = (uint32_t*)(sm + OFF_BLO);

    const int tid  = threadIdx.x;
    const int lane = tid & 31;
    const int wid  = tid >> 5;
    const int wm64 = (wid >> 2) << 6;
    const int wn32 = (wid & 3) << 5;
    const int bm = blockIdx.y << 7;
    const int bn = blockIdx.x << 7;

    float4 rA[4], rB[4];
    const int NKC = K >> 5;

#pragma unroll
    for (int it = 0; it < 4; it++) {
        int i = tid + (it << 8);
        int r = i >> 3, cf = (i & 7) << 2;
        rA[it] = *(const float4*)(A + (size_t)(bm + r) * K + cf);
        rB[it] = *(const float4*)(B + (size_t)(bn + r) * K + cf);
    }

    float acc[4][4][4];
#pragma unroll
    for (int mt = 0; mt < 4; mt++)
#pragma unroll
        for (int nt = 0; nt < 4; nt++)
#pragma unroll
            for (int c = 0; c < 4; c++) acc[mt][nt][c] = 0.f;

    for (int kc = 0; kc < NKC; kc++) {
#pragma unroll
        for (int it = 0; it < 4; it++) {
            int i = tid + (it << 8);
            int r = i >> 3, cf = (i & 7) << 2;
            int off = r * SSTRIDE + cf;
            uint4 hi, lo;
            hi.x = f2tf32(rA[it].x); lo.x = f2tf32(rA[it].x - __uint_as_float(hi.x));
            hi.y = f2tf32(rA[it].y); lo.y = f2tf32(rA[it].y - __uint_as_float(hi.y));
            hi.z = f2tf32(rA[it].z); lo.z = f2tf32(rA[it].z - __uint_as_float(hi.z));
            hi.w = f2tf32(rA[it].w); lo.w = f2tf32(rA[it].w - __uint_as_float(hi.w));
            *(uint4*)(AHI + off) = hi;
            *(uint4*)(ALO + off) = lo;
            hi.x = f2tf32(rB[it].x); lo.x = f2tf32(rB[it].x - __uint_as_float(hi.x));
            hi.y = f2tf32(rB[it].y); lo.y = f2tf32(rB[it].y - __uint_as_float(hi.y));
            hi.z = f2tf32(rB[it].z); lo.z = f2tf32(rB[it].z - __uint_as_float(hi.z));
            hi.w = f2tf32(rB[it].w); lo.w = f2tf32(rB[it].w - __uint_as_float(hi.w));
            *(uint4*)(BHI + off) = hi;
            *(uint4*)(BLO + off) = lo;
        }
        __syncthreads();

        if (kc + 1 < NKC) {
            int k0 = (kc + 1) << 5;
#pragma unroll
            for (int it = 0; it < 4; it++) {
                int i = tid + (it << 8);
                int r = i >> 3, cf = (i & 7) << 2;
                rA[it] = *(const float4*)(A + (size_t)(bm + r) * K + k0 + cf);
                rB[it] = *(const float4*)(B + (size_t)(bn + r) * K + k0 + cf);
            }
        }

#pragma unroll
        for (int kk = 0; kk < 4; kk++) {
            const int kcol = (kk << 3) + (lane & 3);
            uint32_t ahi[4][4], alo[4][4], bhi[4][2], blo[4][2];
#pragma unroll
            for (int mt = 0; mt < 4; mt++) {
                int base = (wm64 + (mt << 4) + (lane >> 2)) * SSTRIDE + kcol;
                ahi[mt][0] = AHI[base];
                ahi[mt][1] = AHI[base + 8 * SSTRIDE];
                ahi[mt][2] = AHI[base + 4];
                ahi[mt][3] = AHI[base + 8 * SSTRIDE + 4];
                alo[mt][0] = ALO[base];
                alo[mt][1] = ALO[base + 8 * SSTRIDE];
                alo[mt][2] = ALO[base + 4];
                alo[mt][3] = ALO[base + 8 * SSTRIDE + 4];
            }
#pragma unroll
            for (int nt = 0; nt < 4; nt++) {
                int base = (wn32 + (nt << 3) + (lane >> 2)) * SSTRIDE + kcol;
                bhi[nt][0] = BHI[base];
                bhi[nt][1] = BHI[base + 4];
                blo[nt][0] = BLO[base];
                blo[nt][1] = BLO[base + 4];
            }
#pragma unroll
            for (int mt = 0; mt < 4; mt++)
#pragma unroll
                for (int nt = 0; nt < 4; nt++)
                    mma_tf32(acc[mt][nt], ahi[mt], bhi[nt]);
#pragma unroll
            for (int mt = 0; mt < 4; mt++)
#pragma unroll
                for (int nt = 0; nt < 4; nt++)
                    mma_tf32(acc[mt][nt], ahi[mt], blo[nt]);
#pragma unroll
            for (int mt = 0; mt < 4; mt++)
#pragma unroll
                for (int nt = 0; nt < 4; nt++)
                    mma_tf32(acc[mt][nt], alo[mt], bhi[nt]);
        }
        __syncthreads();
    }

#pragma unroll
    for (int mt = 0; mt < 4; mt++) {
        int row0 = bm + wm64 + (mt << 4) + (lane >> 2);
#pragma unroll
        for (int nt = 0; nt < 4; nt++) {
            int col0 = bn + wn32 + (nt << 3) + ((lane & 3) << 1);
            float b0 = bias[col0], b1 = bias[col0 + 1];
            float2 v0 = make_float2(acc[mt][nt][0] + b0, acc[mt][nt][1] + b1);
            float2 v1 = make_float2(acc[mt][nt][2] + b0, acc[mt][nt][3] + b1);
            if (RELU) {
                v0.x = fmaxf(v0.x, 0.f); v0.y = fmaxf(v0.y, 0.f);
                v1.x = fmaxf(v1.x, 0.f); v1.y = fmaxf(v1.y, 0.f);
            }
            *(float2*)(C + (size_t)row0 * N + col0) = v0;
            *(float2*)(C + (size_t)(row0 + 8) * N + col0) = v1;
        }
    }
}

// ---------------- zero ----------------
__global__ void zero_kernel(float* __restrict__ p, int n) {
    int i = blockIdx.x * blockDim.x + threadIdx.x;
    if (i < n) p[i] = 0.f;
}

// ---------------- edge-index dtype detection ----------------
__global__ void detect_idx_kernel(const int* __restrict__ ei32) {
    if (threadIdx.x == 0 && blockIdx.x == 0) {
        int allzero = 1;
#pragma unroll
        for (int i = 1; i < 16; i += 2)
            if (ei32[i] != 0) allzero = 0;
        g_idx64_flag = allzero;
    }
}

// ---------------- scatter-add ----------------
__global__ void scatter_add_kernel(const void* __restrict__ ei) {
    int e = blockIdx.x;
    int dst;
    if (g_idx64_flag)
        dst = (int)((const long long*)ei)[E_N + e];
    else
        dst = ((const int*)ei)[E_N + e];
    if ((unsigned)dst >= (unsigned)E_N) return;
    const float* src = g_msg + (size_t)e * H_N;
    float* d = g_agg + (size_t)dst * H_N;
    for (int i = threadIdx.x; i < H_N; i += blockDim.x)
        atomicAdd(&d[i], src[i]);
}

// ---------------- GRU elementwise ----------------
__global__ __launch_bounds__(256) void gru_kernel(const float* __restrict__ x) {
    int idx = blockIdx.x * blockDim.x + threadIdx.x;
    if (idx >= E_N * H_N) return;
    int e = idx / H_N, i = idx - e * H_N;
    const float* gi = g_gi + (size_t)e * H3_N;
    const float* gh = g_gh + (size_t)e * H3_N;
    float r = 1.f / (1.f + __expf(-(gi[i] + gh[i])));
    float z = 1.f / (1.f + __expf(-(gi[H_N + i] + gh[H_N + i])));
    float n = tanhf(gi[2 * H_N + i] + r * gh[2 * H_N + i]);
    g_h[idx] = (1.f - z) * n + z * x[idx];
}

// ---------------- split qkv into per-head tf32 hi/lo planes --------------
__global__ __launch_bounds__(256) void split_qkv_kernel() {
    int idx = blockIdx.x * 256 + threadIdx.x;     // < E_N * H_N
    if (idx >= E_N * H_N) return;
    int e = idx >> 9, c = idx & 511;
    int head = c >> 7, d = c & 127;
    size_t dst = ((size_t)head * E_N + e) * HD_N + d;
    const float scale = 0.08838834764831845f;     // 1/sqrt(128)
    float q = g_qkv[(size_t)e * H3_N + c] * scale;
    uint32_t h = f2tf32(q);
    g_qhi[dst] = h; g_qlo[dst] = f2tf32(q - __uint_as_float(h));
    float k = g_qkv[(size_t)e * H3_N + H_N + c];
    h = f2tf32(k);
    g_khi[dst] = h; g_klo[dst] = f2tf32(k - __uint_as_float(h));
    float v = g_qkv[(size_t)e * H3_N + 2 * H_N + c];
    h = f2tf32(v);
    g_vhi[dst] = h; g_vlo[dst] = f2tf32(v - __uint_as_float(h));
}

// ---------------- flash-attention, mma tf32x3 ----------------
// grid (E/128, NH), block 256 (8 warps). Q tile 128 rows resident, K/V 32.
#define AT_QSTR 132
#define AT_KSTR 132
#define AT_VSTR 136
#define AT_SSTR 36
#define AT_QHI 0
#define AT_QLO (AT_QHI + 128 * AT_QSTR)
#define AT_KHI (AT_QLO + 128 * AT_QSTR)
#define AT_KLO (AT_KHI + 32 * AT_KSTR)
#define AT_VHI (AT_KLO + 32 * AT_KSTR)
#define AT_VLO (AT_VHI + 32 * AT_VSTR)
#define AT_SS  (AT_VLO + 32 * AT_VSTR)
#define AT_MS  (AT_SS + 128 * AT_SSTR)
#define AT_LS  (AT_MS + 128)
#define AT_AS  (AT_LS + 128)
#define AT_TOTAL (AT_AS + 128)
#define ATTN_SMEM_BYTES (AT_TOTAL * 4)

__global__ __launch_bounds__(256) void attn_mma_kernel() {
    extern __shared__ float smf[];
    uint32_t* QHI = (uint32_t*)smf + AT_QHI;
    uint32_t* QLO = (uint32_t*)smf + AT_QLO;
    uint32_t* KHI = (uint32_t*)smf + AT_KHI;
    uint32_t* KLO = (uint32_t*)smf + AT_KLO;
    uint32_t* VHI = (uint32_t*)smf + AT_VHI;
    uint32_t* VLO = (uint32_t*)smf + AT_VLO;
    float* SS  = smf + AT_SS;
    float* m_s = smf + AT_MS;
    float* l_s = smf + AT_LS;
    float* a_s = smf + AT_AS;

    const int t = threadIdx.x;
    const int lane = t & 31;
    const int w = t >> 5;
    const int gid = lane >> 2;
    const int qid = lane & 3;
    const int r0 = (w << 4) + gid;
    const int q0 = blockIdx.x << 7;
    const int head = blockIdx.y;

    // load Q hi/lo tile (128 x 128 words each)
    {
        size_t qb = ((size_t)head * E_N + q0) * HD_N;
        for (int i = t; i < 128 * 32; i += 256) {
            int r = i >> 5, c4 = (i & 31) << 2;
            *(uint4*)&QHI[r * AT_QSTR + c4] = *(const uint4*)&g_qhi[qb + r * HD_N + c4];
            *(uint4*)&QLO[r * AT_QSTR + c4] = *(const uint4*)&g_qlo[qb + r * HD_N + c4];
        }
    }
    if (t < 128) { m_s[t] = -1e30f; l_s[t] = 0.f; }

    float o[16][4];
#pragma unroll
    for (int nf = 0; nf < 16; nf++)
#pragma unroll
        for (int c = 0; c < 4; c++) o[nf][c] = 0.f;

    __syncthreads();

    for (int j0 = 0; j0 < E_N; j0 += 32) {
        // fill K/V hi/lo tiles (32 x 128 words each)
        {
            size_t kb = ((size_t)head * E_N + j0) * HD_N;
            for (int i = t; i < 32 * 32; i += 256) {
                int c = i >> 5, d4 = (i & 31) << 2;
                *(uint4*)&KHI[c * AT_KSTR + d4] = *(const uint4*)&g_khi[kb + c * HD_N + d4];
                *(uint4*)&KLO[c * AT_KSTR + d4] = *(const uint4*)&g_klo[kb + c * HD_N + d4];
                *(uint4*)&VHI[c * AT_VSTR + d4] = *(const uint4*)&g_vhi[kb + c * HD_N + d4];
                *(uint4*)&VLO[c * AT_VSTR + d4] = *(const uint4*)&g_vlo[kb + c * HD_N + d4];
            }
        }
        __syncthreads();

        // ---- S = Qs·K^T, tf32x3; warp tile m16 x n32 ----
        float sacc[4][4];
#pragma unroll
        for (int nf = 0; nf < 4; nf++)
#pragma unroll
            for (int c = 0; c < 4; c++) sacc[nf][c] = 0.f;

#pragma unroll
        for (int ks = 0; ks < 16; ks++) {
            const int k0 = ks << 3;
            uint32_t ahi[4], alo[4];
            int ab = r0 * AT_QSTR + k0 + qid;
            ahi[0] = QHI[ab];
            ahi[1] = QHI[ab + 8 * AT_QSTR];
            ahi[2] = QHI[ab + 4];
            ahi[3] = QHI[ab + 8 * AT_QSTR + 4];
            alo[0] = QLO[ab];
            alo[1] = QLO[ab + 8 * AT_QSTR];
            alo[2] = QLO[ab + 4];
            alo[3] = QLO[ab + 8 * AT_QSTR + 4];
#pragma unroll
            for (int nf = 0; nf < 4; nf++) {
                int bb = (nf * 8 + gid) * AT_KSTR + k0 + qid;
                uint32_t bh[2] = { KHI[bb], KHI[bb + 4] };
                uint32_t bl[2] = { KLO[bb], KLO[bb + 4] };
                mma_tf32(sacc[nf], ahi, bh);
                mma_tf32(sacc[nf], ahi, bl);
                mma_tf32(sacc[nf], alo, bh);
            }
        }
        // store S fragments (scale already folded into Q)
#pragma unroll
        for (int nf = 0; nf < 4; nf++) {
            int cb = nf * 8 + (qid << 1);
            SS[r0 * AT_SSTR + cb]           = sacc[nf][0];
            SS[r0 * AT_SSTR + cb + 1]       = sacc[nf][1];
            SS[(r0 + 8) * AT_SSTR + cb]     = sacc[nf][2];
            SS[(r0 + 8) * AT_SSTR + cb + 1] = sacc[nf][3];
        }
        __syncthreads();

        // ---- online softmax: thread pair per row, 16 cols each ----
        {
            int r = t >> 1, cb = (t & 1) << 4;
            float* srow = &SS[r * AT_SSTR + cb];
            float mloc = -1e30f;
#pragma unroll
            for (int i = 0; i < 16; i++) mloc = fmaxf(mloc, srow[i]);
            mloc = fmaxf(mloc, __shfl_xor_sync(0xffffffffu, mloc, 1));
            float mold = m_s[r];
            float mnew = fmaxf(mold, mloc);
            float ssum = 0.f;
#pragma unroll
            for (int i = 0; i < 16; i++) {
                float p = __expf(srow[i] - mnew);
                srow[i] = p;
                ssum += p;
            }
            ssum += __shfl_xor_sync(0xffffffffu, ssum, 1);
            if (!(t & 1)) {
                float alpha = __expf(mold - mnew);
                m_s[r] = mnew;
                a_s[r] = alpha;
                l_s[r] = l_s[r] * alpha + ssum;
            }
        }
        __syncthreads();

        // ---- O = O*alpha + P·V (tf32x3) ----
        {
            float al0 = a_s[r0], al1 = a_s[r0 + 8];
#pragma unroll
            for (int nf = 0; nf < 16; nf++) {
                o[nf][0] *= al0; o[nf][1] *= al0;
                o[nf][2] *= al1; o[nf][3] *= al1;
            }
        }
#pragma unroll
        for (int ks = 0; ks < 4; ks++) {
            const int k0 = ks << 3;
            float p0 = SS[r0 * AT_SSTR + k0 + qid];
            float p1 = SS[(r0 + 8) * AT_SSTR + k0 + qid];
            float p2 = SS[r0 * AT_SSTR + k0 + qid + 4];
            float p3 = SS[(r0 + 8) * AT_SSTR + k0 + qid + 4];
            uint32_t phi[4], plo[4];
            phi[0] = f2tf32(p0); plo[0] = f2tf32(p0 - __uint_as_float(phi[0]));
            phi[1] = f2tf32(p1); plo[1] = f2tf32(p1 - __uint_as_float(phi[1]));
            phi[2] = f2tf32(p2); plo[2] = f2tf32(p2 - __uint_as_float(phi[2]));
            phi[3] = f2tf32(p3); plo[3] = f2tf32(p3 - __uint_as_float(phi[3]));
#pragma unroll
            for (int nf = 0; nf < 16; nf++) {
                int bb = (k0 + qid) * AT_VSTR + nf * 8 + gid;
                uint32_t bh[2] = { VHI[bb], VHI[bb + 4 * AT_VSTR] };
                uint32_t bl[2] = { VLO[bb], VLO[bb + 4 * AT_VSTR] };
                mma_tf32(o[nf], phi, bh);
                mma_tf32(o[nf], phi, bl);
                mma_tf32(o[nf], plo, bh);
            }
        }
        __syncthreads();
    }

    // ---- epilogue: divide by l, write head-concatenated output ----
    {
        float inv0 = 1.f / l_s[r0];
        float inv1 = 1.f / l_s[r0 + 8];
#pragma unroll
        for (int nf = 0; nf < 16; nf++) {
            int col = head * HD_N + nf * 8 + (qid << 1);
            *(float2*)&g_attn[(size_t)(q0 + r0) * H_N + col] =
                make_float2(o[nf][0] * inv0, o[nf][1] * inv0);
            *(float2*)&g_attn[(size_t)(q0 + r0 + 8) * H_N + col] =
                make_float2(o[nf][2] * inv1, o[nf][3] * inv1);
        }
    }
}

// ---------------- residual + LayerNorm ----------------
__global__ __launch_bounds__(256) void ln_kernel(const float* __restrict__ ln_g,
                                                 const float* __restrict__ ln_b) {
    __shared__ float reda[8], redb[8];
    int e = blockIdx.x;
    const float* yp = g_yprj + (size_t)e * H_N;
    const float* hp = g_h + (size_t)e * H_N;
    int i0 = threadIdx.x, i1 = threadIdx.x + 256;
    float v0 = yp[i0] + hp[i0];
    float v1 = yp[i1] + hp[i1];
    float s = v0 + v1, s2 = v0 * v0 + v1 * v1;
#pragma unroll
    for (int o = 16; o > 0; o >>= 1) {
        s  += __shfl_down_sync(0xffffffffu, s, o);
        s2 += __shfl_down_sync(0xffffffffu, s2, o);
    }
    int w = threadIdx.x >> 5;
    if ((threadIdx.x & 31) == 0) { reda[w] = s; redb[w] = s2; }
    __syncthreads();
    if (threadIdx.x < 8) {
        s = reda[threadIdx.x]; s2 = redb[threadIdx.x];
#pragma unroll
        for (int o = 4; o > 0; o >>= 1) {
            s  += __shfl_down_sync(0xffu, s, o);
            s2 += __shfl_down_sync(0xffu, s2, o);
        }
        if (threadIdx.x == 0) { reda[0] = s; redb[0] = s2; }
    }
    __syncthreads();
    float mu = reda[0] * (1.f / H_N);
    float var = redb[0] * (1.f / H_N) - mu * mu;
    float rstd = rsqrtf(var + 1e-5f);
    g_yn[(size_t)e * H_N + i0] = (v0 - mu) * rstd * ln_g[i0] + ln_b[i0];
    g_yn[(size_t)e * H_N + i1] = (v1 - mu) * rstd * ln_g[i1] + ln_b[i1];
}

// ---------------- final dot ----------------
__global__ __launch_bounds__(256) void final_kernel(const float* __restrict__ W2,
                                                    const float* __restrict__ b2,
                                                    float* __restrict__ out) {
    __shared__ float red[8];
    int e = blockIdx.x;
    const float* fp = g_f + (size_t)e * FFN_N;
    float s = 0.f;
    for (int i = threadIdx.x; i < FFN_N; i += 256) s += fp[i] * W2[i];
#pragma unroll
    for (int o = 16; o > 0; o >>= 1) s += __shfl_down_sync(0xffffffffu, s, o);
    int w = threadIdx.x >> 5;
    if ((threadIdx.x & 31) == 0) red[w] = s;
    __syncthreads();
    if (threadIdx.x < 8) {
        s = red[threadIdx.x];
#pragma unroll
        for (int o = 4; o > 0; o >>= 1) s += __shfl_down_sync(0xffu, s, o);
        if (threadIdx.x == 0) out[e] = s + b2[0];
    }
}

// ---------------- launcher ----------------
extern "C" void kernel_launch(void* const* d_in, const int* in_sizes, int n_in,
                              void* d_out, int out_size) {
    const float* x       = (const float*)d_in[0];
    const void*  ei      = d_in[1];
    const float* W_msg   = (const float*)d_in[2];
    const float* b_msg   = (const float*)d_in[3];
    const float* W_ih    = (const float*)d_in[4];
    const float* b_ih    = (const float*)d_in[5];
    const float* W_hh    = (const float*)d_in[6];
    const float* b_hh    = (const float*)d_in[7];
    const float* W_inp   = (const float*)d_in[8];
    const float* b_inp   = (const float*)d_in[9];
    const float* W_outp  = (const float*)d_in[10];
    const float* b_outp  = (const float*)d_in[11];
    const float* ln_g    = (const float*)d_in[12];
    const float* ln_b    = (const float*)d_in[13];
    const float* W_lin   = (const float*)d_in[14];
    const float* b_lin   = (const float*)d_in[15];
    const float* W_f1    = (const float*)d_in[16];
    const float* b_f1    = (const float*)d_in[17];
    const float* W_f2    = (const float*)d_in[18];
    const float* b_f2    = (const float*)d_in[19];
    float* out = (float*)d_out;

    float *p_msg, *p_agg, *p_gi, *p_gh, *p_h, *p_qkv, *p_yn, *p_gact, *p_f;
    float *p_attn, *p_yprj;
    cudaGetSymbolAddress((void**)&p_msg,  g_msg);
    cudaGetSymbolAddress((void**)&p_agg,  g_agg);
    cudaGetSymbolAddress((void**)&p_gi,   g_gi);
    cudaGetSymbolAddress((void**)&p_gh,   g_gh);
    cudaGetSymbolAddress((void**)&p_h,    g_h);
    cudaGetSymbolAddress((void**)&p_qkv,  g_qkv);
    cudaGetSymbolAddress((void**)&p_yn,   g_yn);
    cudaGetSymbolAddress((void**)&p_gact, g_gact);
    cudaGetSymbolAddress((void**)&p_f,    g_f);
    cudaGetSymbolAddress((void**)&p_attn, g_attn);
    cudaGetSymbolAddress((void**)&p_yprj, g_yprj);

    cudaFuncSetAttribute(gemm_mma<false>, cudaFuncAttributeMaxDynamicSharedMemorySize, GEMM_SMEM_BYTES);
    cudaFuncSetAttribute(gemm_mma<true>,  cudaFuncAttributeMaxDynamicSharedMemorySize, GEMM_SMEM_BYTES);
    cudaFuncSetAttribute(attn_mma_kernel,  cudaFuncAttributeMaxDynamicSharedMemorySize, ATTN_SMEM_BYTES);

    // 0) detect edge_index dtype
    detect_idx_kernel<<<1, 32>>>((const int*)ei);
    // 1) zero agg
    zero_kernel<<<(E_N * H_N + 255) / 256, 256>>>(p_agg, E_N * H_N);
    // 2) msg = relu(x @ W_msg^T + b)
    gemm_mma<true><<<dim3(H_N / 128, E_N / 128), 256, GEMM_SMEM_BYTES>>>(x, W_msg, b_msg, p_msg, H_N, H_N);
    // 3) scatter-add
    scatter_add_kernel<<<E_N, 128>>>(ei);
    // 4) gi, gh
    gemm_mma<false><<<dim3(H3_N / 128, E_N / 128), 256, GEMM_SMEM_BYTES>>>(p_agg, W_ih, b_ih, p_gi, H3_N, H_N);
    gemm_mma<false><<<dim3(H3_N / 128, E_N / 128), 256, GEMM_SMEM_BYTES>>>(x, W_hh, b_hh, p_gh, H3_N, H_N);
    // 5) GRU
    gru_kernel<<<(E_N * H_N + 255) / 256, 256>>>(x);
    // 6) qkv
    gemm_mma<false><<<dim3(H3_N / 128, E_N / 128), 256, GEMM_SMEM_BYTES>>>(p_h, W_inp, b_inp, p_qkv, H3_N, H_N);
    // 7) split qkv into tf32 hi/lo planes, then mma attention
    split_qkv_kernel<<<(E_N * H_N + 255) / 256, 256>>>();
    attn_mma_kernel<<<dim3(E_N / 128, NH_N), 256, ATTN_SMEM_BYTES>>>();
    // 8) out-proj
    gemm_mma<false><<<dim3(H_N / 128, E_N / 128), 256, GEMM_SMEM_BYTES>>>(p_attn, W_outp, b_outp, p_yprj, H_N, H_N);
    // 9) residual + LN
    ln_kernel<<<E_N, 256>>>(ln_g, ln_b);
    // 10) g = relu(yn @ W_lin^T + b)
    gemm_mma<true><<<dim3(H_N / 128, E_N / 128), 256, GEMM_SMEM_BYTES>>>(p_yn, W_lin, b_lin, p_gact, H_N, H_N);
    // 11) f = relu(g @ W_f1^T + b_f1)
    gemm_mma<true><<<dim3(FFN_N / 128, E_N / 128), 256, GEMM_SMEM_BYTES>>>(p_gact, W_f1, b_f1, p_f, FFN_N, H_N);
    // 12) out
    final_kernel<<<E_N, 256>>>(W_f2, b_f2, out);
}

// round 6
// speedup vs baseline: 3.4687x; 1.5977x over previous
#include <cuda_runtime.h>
#include <cuda_bf16.h>
#include <math.h>
#include <stdint.h>

#define E_N   4096
#define H_N   512
#define NH_N  4
#define HD_N  128
#define FFN_N 1024
#define H3_N  1536

// ---------------- scratch (static __device__, no allocs) ----------------
__device__ float g_msg [E_N * H_N];
__device__ float g_agg [E_N * H_N];
__device__ float g_gi  [E_N * H3_N];
__device__ float g_gh  [E_N * H3_N];
__device__ float g_h   [E_N * H_N];
__device__ float g_qkv [E_N * H3_N];
__device__ float g_attn[E_N * H_N];
__device__ float g_yprj[E_N * H_N];
__device__ float g_yn  [E_N * H_N];
__device__ float g_gact[E_N * H_N];
__device__ float g_f   [E_N * FFN_N];
__device__ int   g_idx64_flag;
// packed bf16x2 hi/lo planes. Q/K: [NH][E][HD/2] words. VT: [NH][HD][E/2] words.
__device__ uint32_t g_qhi [NH_N * E_N * (HD_N / 2)];
__device__ uint32_t g_qlo [NH_N * E_N * (HD_N / 2)];
__device__ uint32_t g_khi [NH_N * E_N * (HD_N / 2)];
__device__ uint32_t g_klo [NH_N * E_N * (HD_N / 2)];
__device__ uint32_t g_vthi[NH_N * HD_N * (E_N / 2)];
__device__ uint32_t g_vtlo[NH_N * HD_N * (E_N / 2)];

// ================= helpers =================
__device__ __forceinline__ uint32_t smem_u32(const void* p) {
    uint32_t a;
    asm("{ .reg .u64 t; cvta.to.shared.u64 t, %1; cvt.u32.u64 %0, t; }"
        : "=r"(a) : "l"(p));
    return a;
}

// split (x,y) into packed bf16x2 hi and lo words (x -> low half)
__device__ __forceinline__ void pack2(float x, float y, uint32_t& hi, uint32_t& lo) {
    __nv_bfloat162 h = __floats2bfloat162_rn(x, y);
    float hx = __bfloat162float(__low2bfloat16(h));
    float hy = __bfloat162float(__high2bfloat16(h));
    __nv_bfloat162 l = __floats2bfloat162_rn(x - hx, y - hy);
    hi = *reinterpret_cast<uint32_t*>(&h);
    lo = *reinterpret_cast<uint32_t*>(&l);
}

__device__ __forceinline__ void mma_bf16(float* d, const uint32_t* a, const uint32_t* b) {
    asm volatile(
        "mma.sync.aligned.m16n8k16.row.col.f32.bf16.bf16.f32 "
        "{%0,%1,%2,%3}, {%4,%5,%6,%7}, {%8,%9}, {%0,%1,%2,%3};"
        : "+f"(d[0]), "+f"(d[1]), "+f"(d[2]), "+f"(d[3])
        : "r"(a[0]), "r"(a[1]), "r"(a[2]), "r"(a[3]),
          "r"(b[0]), "r"(b[1]));
}

__device__ __forceinline__ void ldm_x4(uint32_t* r, uint32_t addr) {
    asm volatile("ldmatrix.sync.aligned.m8n8.x4.shared.b16 {%0,%1,%2,%3}, [%4];"
        : "=r"(r[0]), "=r"(r[1]), "=r"(r[2]), "=r"(r[3]) : "r"(addr));
}
__device__ __forceinline__ void ldm_x2(uint32_t* r, uint32_t addr) {
    asm volatile("ldmatrix.sync.aligned.m8n8.x2.shared.b16 {%0,%1}, [%2];"
        : "=r"(r[0]), "=r"(r[1]) : "r"(addr));
}

// ================= bf16x3 GEMM ==============================
// C[M,N] = A[M,K] @ B[N,K]^T + bias, optional ReLU.
// CTA tile 128x128, 8 warps 2(M)x4(N), warp 64x32 = 4x4 m16n8 frags.
// K chunk 32 fp32 = 16 packed words/row; smem stride 20 words.
#define WSTR 20
#define PLANE_WORDS (128 * WSTR)
#define PLANE_BYTES (PLANE_WORDS * 4)
#define GEMM_SMEM_BYTES (4 * PLANE_BYTES)   // 40960

template <bool RELU>
__global__ __launch_bounds__(256) void gemm_bf16(
    const float* __restrict__ A, const float* __restrict__ B,
    const float* __restrict__ bias, float* __restrict__ C,
    int N, int K)
{
    extern __shared__ uint32_t smw[];
    uint32_t* AHI = smw;
    uint32_t* ALO = smw + PLANE_WORDS;
    uint32_t* BHI = smw + 2 * PLANE_WORDS;
    uint32_t* BLO = smw + 3 * PLANE_WORDS;
    const uint32_t sb = smem_u32(smw);

    const int tid  = threadIdx.x;
    const int lane = tid & 31;
    const int wid  = tid >> 5;
    const int wm64 = (wid >> 2) << 6;
    const int wn32 = (wid & 3) << 5;
    const int bm = blockIdx.y << 7;
    const int bn = blockIdx.x << 7;

    float4 rA[4], rB[4];
    const int NKC = K >> 5;

#pragma unroll
    for (int it = 0; it < 4; it++) {
        int i = tid + (it << 8);
        int r = i >> 3, cf = (i & 7) << 2;
        rA[it] = *(const float4*)(A + (size_t)(bm + r) * K + cf);
        rB[it] = *(const float4*)(B + (size_t)(bn + r) * K + cf);
    }

    float acc[4][4][4];
#pragma unroll
    for (int mt = 0; mt < 4; mt++)
#pragma unroll
        for (int nt = 0; nt < 4; nt++)
#pragma unroll
            for (int c = 0; c < 4; c++) acc[mt][nt][c] = 0.f;

    for (int kc = 0; kc < NKC; kc++) {
        // ---- pack prefetched chunk into smem hi/lo bf16 planes ----
#pragma unroll
        for (int it = 0; it < 4; it++) {
            int i = tid + (it << 8);
            int r = i >> 3, w0 = (i & 7) << 1;
            int off = r * WSTR + w0;
            uint32_t h0, h1, l0, l1;
            pack2(rA[it].x, rA[it].y, h0, l0);
            pack2(rA[it].z, rA[it].w, h1, l1);
            AHI[off] = h0; AHI[off + 1] = h1;
            ALO[off] = l0; ALO[off + 1] = l1;
            pack2(rB[it].x, rB[it].y, h0, l0);
            pack2(rB[it].z, rB[it].w, h1, l1);
            BHI[off] = h0; BHI[off + 1] = h1;
            BLO[off] = l0; BLO[off + 1] = l1;
        }
        __syncthreads();

        if (kc + 1 < NKC) {
            int k0 = (kc + 1) << 5;
#pragma unroll
            for (int it = 0; it < 4; it++) {
                int i = tid + (it << 8);
                int r = i >> 3, cf = (i & 7) << 2;
                rA[it] = *(const float4*)(A + (size_t)(bm + r) * K + k0 + cf);
                rB[it] = *(const float4*)(B + (size_t)(bn + r) * K + k0 + cf);
            }
        }

        // ---- 2 k16 steps, bf16x3 ----
#pragma unroll
        for (int ks = 0; ks < 2; ks++) {
            const int kw = ks << 3;
            uint32_t ahi[4][4], alo[4][4];
#pragma unroll
            for (int mt = 0; mt < 4; mt++) {
                uint32_t bo = (uint32_t)(((wm64 + (mt << 4) + (lane & 15)) * WSTR
                                          + kw + ((lane >> 4) << 2)) << 2);
                ldm_x4(ahi[mt], sb + bo);
                ldm_x4(alo[mt], sb + PLANE_BYTES + bo);
            }
            uint32_t bhi[4][2], blo[4][2];
#pragma unroll
            for (int nt = 0; nt < 4; nt++) {
                uint32_t bo = (uint32_t)(((wn32 + (nt << 3) + (lane & 7)) * WSTR
                                          + kw + (((lane >> 3) & 1) << 2)) << 2);
                ldm_x2(bhi[nt], sb + 2 * PLANE_BYTES + bo);
                ldm_x2(blo[nt], sb + 3 * PLANE_BYTES + bo);
            }
#pragma unroll
            for (int mt = 0; mt < 4; mt++)
#pragma unroll
                for (int nt = 0; nt < 4; nt++)
                    mma_bf16(acc[mt][nt], ahi[mt], bhi[nt]);
#pragma unroll
            for (int mt = 0; mt < 4; mt++)
#pragma unroll
                for (int nt = 0; nt < 4; nt++)
                    mma_bf16(acc[mt][nt], ahi[mt], blo[nt]);
#pragma unroll
            for (int mt = 0; mt < 4; mt++)
#pragma unroll
                for (int nt = 0; nt < 4; nt++)
                    mma_bf16(acc[mt][nt], alo[mt], bhi[nt]);
        }
        __syncthreads();
    }

#pragma unroll
    for (int mt = 0; mt < 4; mt++) {
        int row0 = bm + wm64 + (mt << 4) + (lane >> 2);
#pragma unroll
        for (int nt = 0; nt < 4; nt++) {
            int col0 = bn + wn32 + (nt << 3) + ((lane & 3) << 1);
            float b0 = bias[col0], b1 = bias[col0 + 1];
            float2 v0 = make_float2(acc[mt][nt][0] + b0, acc[mt][nt][1] + b1);
            float2 v1 = make_float2(acc[mt][nt][2] + b0, acc[mt][nt][3] + b1);
            if (RELU) {
                v0.x = fmaxf(v0.x, 0.f); v0.y = fmaxf(v0.y, 0.f);
                v1.x = fmaxf(v1.x, 0.f); v1.y = fmaxf(v1.y, 0.f);
            }
            *(float2*)(C + (size_t)row0 * N + col0) = v0;
            *(float2*)(C + (size_t)(row0 + 8) * N + col0) = v1;
        }
    }
}

// ---------------- zero ----------------
__global__ void zero_kernel(float* __restrict__ p, int n) {
    int i = blockIdx.x * blockDim.x + threadIdx.x;
    if (i < n) p[i] = 0.f;
}

// ---------------- edge-index dtype detection ----------------
__global__ void detect_idx_kernel(const int* __restrict__ ei32) {
    if (threadIdx.x == 0 && blockIdx.x == 0) {
        int allzero = 1;
#pragma unroll
        for (int i = 1; i < 16; i += 2)
            if (ei32[i] != 0) allzero = 0;
        g_idx64_flag = allzero;
    }
}

// ---------------- scatter-add ----------------
__global__ void scatter_add_kernel(const void* __restrict__ ei) {
    int e = blockIdx.x;
    int dst;
    if (g_idx64_flag)
        dst = (int)((const long long*)ei)[E_N + e];
    else
        dst = ((const int*)ei)[E_N + e];
    if ((unsigned)dst >= (unsigned)E_N) return;
    const float* src = g_msg + (size_t)e * H_N;
    float* d = g_agg + (size_t)dst * H_N;
    for (int i = threadIdx.x; i < H_N; i += blockDim.x)
        atomicAdd(&d[i], src[i]);
}

// ---------------- GRU elementwise ----------------
__global__ __launch_bounds__(256) void gru_kernel(const float* __restrict__ x) {
    int idx = blockIdx.x * blockDim.x + threadIdx.x;
    if (idx >= E_N * H_N) return;
    int e = idx / H_N, i = idx - e * H_N;
    const float* gi = g_gi + (size_t)e * H3_N;
    const float* gh = g_gh + (size_t)e * H3_N;
    float r = 1.f / (1.f + __expf(-(gi[i] + gh[i])));
    float z = 1.f / (1.f + __expf(-(gi[H_N + i] + gh[H_N + i])));
    float n = tanhf(gi[2 * H_N + i] + r * gh[2 * H_N + i]);
    g_h[idx] = (1.f - z) * n + z * x[idx];
}

// ---------------- split Q/K into packed bf16 hi/lo (pairs along d) ------
__global__ __launch_bounds__(256) void split_qk_kernel() {
    int idx = blockIdx.x * 256 + threadIdx.x;   // < E_N * 256
    if (idx >= E_N * 256) return;
    int e = idx >> 8, p = idx & 255;
    int head = p >> 6, dp = p & 63;
    const float scale = 0.08838834764831845f;   // 1/sqrt(128)
    size_t src = (size_t)e * H3_N + head * HD_N + (dp << 1);
    uint32_t h, l;
    pack2(g_qkv[src] * scale, g_qkv[src + 1] * scale, h, l);
    size_t dst = ((size_t)head * E_N + e) * 64 + dp;
    g_qhi[dst] = h; g_qlo[dst] = l;
    pack2(g_qkv[src + H_N], g_qkv[src + H_N + 1], h, l);
    g_khi[dst] = h; g_klo[dst] = l;
}

// ---------------- split V transposed: pairs along e ---------------------
__global__ __launch_bounds__(256) void split_vt_kernel() {
    int idx = blockIdx.x * 256 + threadIdx.x;   // < (E_N/2) * H_N
    if (idx >= (E_N / 2) * H_N) return;
    int ep = idx >> 9, c = idx & 511;
    int head = c >> 7, d = c & 127;
    float v0 = g_qkv[(size_t)(2 * ep) * H3_N + 2 * H_N + c];
    float v1 = g_qkv[(size_t)(2 * ep + 1) * H3_N + 2 * H_N + c];
    uint32_t h, l;
    pack2(v0, v1, h, l);
    size_t dst = ((size_t)head * HD_N + d) * (E_N / 2) + ep;
    g_vthi[dst] = h; g_vtlo[dst] = l;
}

// ---------------- flash-attention, bf16x3 mma ----------------
// grid (E/128, NH), block 256. Q tile 128 resident; K/V tiles BC=32.
#define AQ_STR 68
#define AK_STR 68
#define AV_STR 20
#define AS_STR 36
#define AT_QHI 0
#define AT_QLO (AT_QHI + 128 * AQ_STR)
#define AT_KHI (AT_QLO + 128 * AQ_STR)
#define AT_KLO (AT_KHI + 32 * AK_STR)
#define AT_VHI (AT_KLO + 32 * AK_STR)
#define AT_VLO (AT_VHI + 128 * AV_STR)
#define AT_SS  (AT_VLO + 128 * AV_STR)
#define AT_MS  (AT_SS + 128 * AS_STR)
#define AT_LS  (AT_MS + 128)
#define AT_AS  (AT_LS + 128)
#define AT_TOTAL (AT_AS + 128)
#define ATTN_SMEM_BYTES (AT_TOTAL * 4)

__global__ __launch_bounds__(256) void attn_bf16_kernel() {
    extern __shared__ uint32_t smw[];
    const uint32_t sb = smem_u32(smw);
    float* SS  = (float*)(smw + AT_SS);
    float* m_s = (float*)(smw + AT_MS);
    float* l_s = (float*)(smw + AT_LS);
    float* a_s = (float*)(smw + AT_AS);

    const int t = threadIdx.x;
    const int lane = t & 31;
    const int w = t >> 5;
    const int gid = lane >> 2;
    const int qid = lane & 3;
    const int r0 = (w << 4) + gid;
    const int q0 = blockIdx.x << 7;
    const int head = blockIdx.y;

    // Q tile fill: 128 rows x 64 words per plane
    {
        size_t qb = ((size_t)head * E_N + q0) * 64;
        for (int i = t; i < 2048; i += 256) {
            int r = i >> 4, w4 = (i & 15) << 2;
            *(uint4*)(smw + AT_QHI + r * AQ_STR + w4) = *(const uint4*)&g_qhi[qb + r * 64 + w4];
            *(uint4*)(smw + AT_QLO + r * AQ_STR + w4) = *(const uint4*)&g_qlo[qb + r * 64 + w4];
        }
    }
    if (t < 128) { m_s[t] = -1e30f; l_s[t] = 0.f; }

    float o[16][4];
#pragma unroll
    for (int nf = 0; nf < 16; nf++)
#pragma unroll
        for (int c = 0; c < 4; c++) o[nf][c] = 0.f;

    __syncthreads();

    for (int j0 = 0; j0 < E_N; j0 += 32) {
        // K tile: 32 rows x 64 words; VT tile: 128 rows x 16 words
        {
            size_t kb = ((size_t)head * E_N + j0) * 64;
            for (int i = t; i < 512; i += 256) {
                int r = i >> 4, w4 = (i & 15) << 2;
                *(uint4*)(smw + AT_KHI + r * AK_STR + w4) = *(const uint4*)&g_khi[kb + r * 64 + w4];
                *(uint4*)(smw + AT_KLO + r * AK_STR + w4) = *(const uint4*)&g_klo[kb + r * 64 + w4];
            }
            size_t vb = (size_t)head * HD_N * (E_N / 2) + (j0 >> 1);
            for (int i = t; i < 512; i += 256) {
                int r = i >> 2, w4 = (i & 3) << 2;
                *(uint4*)(smw + AT_VHI + r * AV_STR + w4) =
                    *(const uint4*)&g_vthi[vb + (size_t)r * (E_N / 2) + w4];
                *(uint4*)(smw + AT_VLO + r * AV_STR + w4) =
                    *(const uint4*)&g_vtlo[vb + (size_t)r * (E_N / 2) + w4];
            }
        }
        __syncthreads();

        // ---- S = Q K^T, bf16x3; 8 k16 steps ----
        float sacc[4][4];
#pragma unroll
        for (int nf = 0; nf < 4; nf++)
#pragma unroll
            for (int c = 0; c < 4; c++) sacc[nf][c] = 0.f;

#pragma unroll
        for (int ks = 0; ks < 8; ks++) {
            const int kw = ks << 3;
            uint32_t ahi[4], alo[4];
            uint32_t ao = (uint32_t)(((AT_QHI + ((w << 4) + (lane & 15)) * AQ_STR
                                       + kw + ((lane >> 4) << 2))) << 2);
            ldm_x4(ahi, sb + ao);
            ldm_x4(alo, sb + ao + (uint32_t)((AT_QLO - AT_QHI) << 2));
#pragma unroll
            for (int nf = 0; nf < 4; nf++) {
                uint32_t bo = (uint32_t)(((AT_KHI + ((nf << 3) + (lane & 7)) * AK_STR
                                           + kw + (((lane >> 3) & 1) << 2))) << 2);
                uint32_t bh[2], bl[2];
                ldm_x2(bh, sb + bo);
                ldm_x2(bl, sb + bo + (uint32_t)((AT_KLO - AT_KHI) << 2));
                mma_bf16(sacc[nf], ahi, bh);
                mma_bf16(sacc[nf], ahi, bl);
                mma_bf16(sacc[nf], alo, bh);
            }
        }
#pragma unroll
        for (int nf = 0; nf < 4; nf++) {
            int cb = (nf << 3) + (qid << 1);
            SS[r0 * AS_STR + cb]           = sacc[nf][0];
            SS[r0 * AS_STR + cb + 1]       = sacc[nf][1];
            SS[(r0 + 8) * AS_STR + cb]     = sacc[nf][2];
            SS[(r0 + 8) * AS_STR + cb + 1] = sacc[nf][3];
        }
        __syncthreads();

        // ---- online softmax: thread pair per row ----
        {
            int r = t >> 1, cb = (t & 1) << 4;
            float* srow = &SS[r * AS_STR + cb];
            float mloc = -1e30f;
#pragma unroll
            for (int i = 0; i < 16; i++) mloc = fmaxf(mloc, srow[i]);
            mloc = fmaxf(mloc, __shfl_xor_sync(0xffffffffu, mloc, 1));
            float mold = m_s[r];
            float mnew = fmaxf(mold, mloc);
            float ssum = 0.f;
#pragma unroll
            for (int i = 0; i < 16; i++) {
                float p = __expf(srow[i] - mnew);
                srow[i] = p;
                ssum += p;
            }
            ssum += __shfl_xor_sync(0xffffffffu, ssum, 1);
            if (!(t & 1)) {
                float alpha = __expf(mold - mnew);
                m_s[r] = mnew;
                a_s[r] = alpha;
                l_s[r] = l_s[r] * alpha + ssum;
            }
        }
        __syncthreads();

        // ---- O = O*alpha + P V (bf16x3), 2 k16 steps ----
        {
            float al0 = a_s[r0], al1 = a_s[r0 + 8];
#pragma unroll
            for (int nf = 0; nf < 16; nf++) {
                o[nf][0] *= al0; o[nf][1] *= al0;
                o[nf][2] *= al1; o[nf][3] *= al1;
            }
        }
#pragma unroll
        for (int ks = 0; ks < 2; ks++) {
            const int k0 = ks << 4;
            float p00 = SS[r0 * AS_STR + k0 + (qid << 1)];
            float p01 = SS[r0 * AS_STR + k0 + (qid << 1) + 1];
            float p10 = SS[(r0 + 8) * AS_STR + k0 + (qid << 1)];
            float p11 = SS[(r0 + 8) * AS_STR + k0 + (qid << 1) + 1];
            float p20 = SS[r0 * AS_STR + k0 + 8 + (qid << 1)];
            float p21 = SS[r0 * AS_STR + k0 + 8 + (qid << 1) + 1];
            float p30 = SS[(r0 + 8) * AS_STR + k0 + 8 + (qid << 1)];
            float p31 = SS[(r0 + 8) * AS_STR + k0 + 8 + (qid << 1) + 1];
            uint32_t phi[4], plo[4];
            pack2(p00, p01, phi[0], plo[0]);
            pack2(p10, p11, phi[1], plo[1]);
            pack2(p20, p21, phi[2], plo[2]);
            pack2(p30, p31, phi[3], plo[3]);
#pragma unroll
            for (int nf = 0; nf < 16; nf++) {
                uint32_t bo = (uint32_t)(((AT_VHI + ((nf << 3) + (lane & 7)) * AV_STR
                                           + (ks << 3) + (((lane >> 3) & 1) << 2))) << 2);
                uint32_t bh[2], bl[2];
                ldm_x2(bh, sb + bo);
                ldm_x2(bl, sb + bo + (uint32_t)((AT_VLO - AT_VHI) << 2));
                mma_bf16(o[nf], phi, bh);
                mma_bf16(o[nf], phi, bl);
                mma_bf16(o[nf], plo, bh);
            }
        }
        __syncthreads();
    }

    // ---- epilogue ----
    {
        float inv0 = 1.f / l_s[r0];
        float inv1 = 1.f / l_s[r0 + 8];
#pragma unroll
        for (int nf = 0; nf < 16; nf++) {
            int col = head * HD_N + (nf << 3) + (qid << 1);
            *(float2*)&g_attn[(size_t)(q0 + r0) * H_N + col] =
                make_float2(o[nf][0] * inv0, o[nf][1] * inv0);
            *(float2*)&g_attn[(size_t)(q0 + r0 + 8) * H_N + col] =
                make_float2(o[nf][2] * inv1, o[nf][3] * inv1);
        }
    }
}

// ---------------- residual + LayerNorm ----------------
__global__ __launch_bounds__(256) void ln_kernel(const float* __restrict__ ln_g,
                                                 const float* __restrict__ ln_b) {
    __shared__ float reda[8], redb[8];
    int e = blockIdx.x;
    const float* yp = g_yprj + (size_t)e * H_N;
    const float* hp = g_h + (size_t)e * H_N;
    int i0 = threadIdx.x, i1 = threadIdx.x + 256;
    float v0 = yp[i0] + hp[i0];
    float v1 = yp[i1] + hp[i1];
    float s = v0 + v1, s2 = v0 * v0 + v1 * v1;
#pragma unroll
    for (int o = 16; o > 0; o >>= 1) {
        s  += __shfl_down_sync(0xffffffffu, s, o);
        s2 += __shfl_down_sync(0xffffffffu, s2, o);
    }
    int w = threadIdx.x >> 5;
    if ((threadIdx.x & 31) == 0) { reda[w] = s; redb[w] = s2; }
    __syncthreads();
    if (threadIdx.x < 8) {
        s = reda[threadIdx.x]; s2 = redb[threadIdx.x];
#pragma unroll
        for (int o = 4; o > 0; o >>= 1) {
            s  += __shfl_down_sync(0xffu, s, o);
            s2 += __shfl_down_sync(0xffu, s2, o);
        }
        if (threadIdx.x == 0) { reda[0] = s; redb[0] = s2; }
    }
    __syncthreads();
    float mu = reda[0] * (1.f / H_N);
    float var = redb[0] * (1.f / H_N) - mu * mu;
    float rstd = rsqrtf(var + 1e-5f);
    g_yn[(size_t)e * H_N + i0] = (v0 - mu) * rstd * ln_g[i0] + ln_b[i0];
    g_yn[(size_t)e * H_N + i1] = (v1 - mu) * rstd * ln_g[i1] + ln_b[i1];
}

// ---------------- final dot ----------------
__global__ __launch_bounds__(256) void final_kernel(const float* __restrict__ W2,
                                                    const float* __restrict__ b2,
                                                    float* __restrict__ out) {
    __shared__ float red[8];
    int e = blockIdx.x;
    const float* fp = g_f + (size_t)e * FFN_N;
    float s = 0.f;
    for (int i = threadIdx.x; i < FFN_N; i += 256) s += fp[i] * W2[i];
#pragma unroll
    for (int o = 16; o > 0; o >>= 1) s += __shfl_down_sync(0xffffffffu, s, o);
    int w = threadIdx.x >> 5;
    if ((threadIdx.x & 31) == 0) red[w] = s;
    __syncthreads();
    if (threadIdx.x < 8) {
        s = red[threadIdx.x];
#pragma unroll
        for (int o = 4; o > 0; o >>= 1) s += __shfl_down_sync(0xffu, s, o);
        if (threadIdx.x == 0) out[e] = s + b2[0];
    }
}

// ---------------- launcher ----------------
extern "C" void kernel_launch(void* const* d_in, const int* in_sizes, int n_in,
                              void* d_out, int out_size) {
    const float* x       = (const float*)d_in[0];
    const void*  ei      = d_in[1];
    const float* W_msg   = (const float*)d_in[2];
    const float* b_msg   = (const float*)d_in[3];
    const float* W_ih    = (const float*)d_in[4];
    const float* b_ih    = (const float*)d_in[5];
    const float* W_hh    = (const float*)d_in[6];
    const float* b_hh    = (const float*)d_in[7];
    const float* W_inp   = (const float*)d_in[8];
    const float* b_inp   = (const float*)d_in[9];
    const float* W_outp  = (const float*)d_in[10];
    const float* b_outp  = (const float*)d_in[11];
    const float* ln_g    = (const float*)d_in[12];
    const float* ln_b    = (const float*)d_in[13];
    const float* W_lin   = (const float*)d_in[14];
    const float* b_lin   = (const float*)d_in[15];
    const float* W_f1    = (const float*)d_in[16];
    const float* b_f1    = (const float*)d_in[17];
    const float* W_f2    = (const float*)d_in[18];
    const float* b_f2    = (const float*)d_in[19];
    float* out = (float*)d_out;

    float *p_msg, *p_agg, *p_gi, *p_gh, *p_h, *p_qkv, *p_yn, *p_gact, *p_f;
    float *p_attn, *p_yprj;
    cudaGetSymbolAddress((void**)&p_msg,  g_msg);
    cudaGetSymbolAddress((void**)&p_agg,  g_agg);
    cudaGetSymbolAddress((void**)&p_gi,   g_gi);
    cudaGetSymbolAddress((void**)&p_gh,   g_gh);
    cudaGetSymbolAddress((void**)&p_h,    g_h);
    cudaGetSymbolAddress((void**)&p_qkv,  g_qkv);
    cudaGetSymbolAddress((void**)&p_yn,   g_yn);
    cudaGetSymbolAddress((void**)&p_gact, g_gact);
    cudaGetSymbolAddress((void**)&p_f,    g_f);
    cudaGetSymbolAddress((void**)&p_attn, g_attn);
    cudaGetSymbolAddress((void**)&p_yprj, g_yprj);

    cudaFuncSetAttribute(gemm_bf16<false>, cudaFuncAttributeMaxDynamicSharedMemorySize, GEMM_SMEM_BYTES);
    cudaFuncSetAttribute(gemm_bf16<true>,  cudaFuncAttributeMaxDynamicSharedMemorySize, GEMM_SMEM_BYTES);
    cudaFuncSetAttribute(attn_bf16_kernel, cudaFuncAttributeMaxDynamicSharedMemorySize, ATTN_SMEM_BYTES);

    // 0) detect edge_index dtype
    detect_idx_kernel<<<1, 32>>>((const int*)ei);
    // 1) zero agg
    zero_kernel<<<(E_N * H_N + 255) / 256, 256>>>(p_agg, E_N * H_N);
    // 2) msg = relu(x @ W_msg^T + b)
    gemm_bf16<true><<<dim3(H_N / 128, E_N / 128), 256, GEMM_SMEM_BYTES>>>(x, W_msg, b_msg, p_msg, H_N, H_N);
    // 3) scatter-add
    scatter_add_kernel<<<E_N, 128>>>(ei);
    // 4) gi, gh
    gemm_bf16<false><<<dim3(H3_N / 128, E_N / 128), 256, GEMM_SMEM_BYTES>>>(p_agg, W_ih, b_ih, p_gi, H3_N, H_N);
    gemm_bf16<false><<<dim3(H3_N / 128, E_N / 128), 256, GEMM_SMEM_BYTES>>>(x, W_hh, b_hh, p_gh, H3_N, H_N);
    // 5) GRU
    gru_kernel<<<(E_N * H_N + 255) / 256, 256>>>(x);
    // 6) qkv
    gemm_bf16<false><<<dim3(H3_N / 128, E_N / 128), 256, GEMM_SMEM_BYTES>>>(p_h, W_inp, b_inp, p_qkv, H3_N, H_N);
    // 7) splits + attention
    split_qk_kernel<<<(E_N * 256) / 256, 256>>>();
    split_vt_kernel<<<((E_N / 2) * H_N) / 256, 256>>>();
    attn_bf16_kernel<<<dim3(E_N / 128, NH_N), 256, ATTN_SMEM_BYTES>>>();
    // 8) out-proj
    gemm_bf16<false><<<dim3(H_N / 128, E_N / 128), 256, GEMM_SMEM_BYTES>>>(p_attn, W_outp, b_outp, p_yprj, H_N, H_N);
    // 9) residual + LN
    ln_kernel<<<E_N, 256>>>(ln_g, ln_b);
    // 10) g = relu(yn @ W_lin^T + b)
    gemm_bf16<true><<<dim3(H_N / 128, E_N / 128), 256, GEMM_SMEM_BYTES>>>(p_yn, W_lin, b_lin, p_gact, H_N, H_N);
    // 11) f = relu(g @ W_f1^T + b_f1)
    gemm_bf16<true><<<dim3(FFN_N / 128, E_N / 128), 256, GEMM_SMEM_BYTES>>>(p_gact, W_f1, b_f1, p_f, FFN_N, H_N);
    // 12) out
    final_kernel<<<E_N, 256>>>(W_f2, b_f2, out);
}